// round 5
// baseline (speedup 1.0000x reference)
#include <cuda_runtime.h>
#include <cuda_bf16.h>
#include <math.h>
#include <stdint.h>

#define Mn  8192
#define En  512
#define INn 384
#define TKn 6
#define NTILE (Mn / 128)   // 64 column tiles

typedef __nv_bfloat16 bf16;

// ------------------------- scratch (__device__ globals; no allocation) -----
__device__ float g_H  [Mn * En];
__device__ float g_EH [Mn * En];
__device__ float g_ET [Mn * En];
__device__ bf16  g_AH[Mn * En];
__device__ bf16  g_AL[Mn * En];
__device__ bf16  g_BH[Mn * En];
__device__ bf16  g_BL[Mn * En];
__device__ bf16  g_XH[Mn * INn];
__device__ bf16  g_XL[Mn * INn];
__device__ bf16  g_HH[Mn * En];
__device__ bf16  g_HL[Mn * En];
__device__ bf16  g_UH[Mn * En];
__device__ bf16  g_UL[Mn * En];
__device__ bf16  g_VH[Mn * En];
__device__ bf16  g_VL[Mn * En];
__device__ bf16  g_MH[Mn * En];
__device__ bf16  g_ML[Mn * En];
__device__ bf16  g_WH[En * En];
__device__ bf16  g_WL[En * En];
__device__ float g_PV [NTILE * Mn * TKn];   // per-tile partial top-6 values
__device__ int   g_PIx[NTILE * Mn * TKn];   // per-tile partial top-6 indices
__device__ float g_TKV[Mn * TKn];
__device__ int   g_TKI[Mn * TKn];
__device__ float g_EMB[Mn * En];
__device__ float g_G1 [Mn * (En / 2)];
__device__ float g_GV [Mn];
__device__ float g_ATT[Mn];
__device__ float g_PART[256 * En];
__device__ float g_CM [En];

// ===================== helpers ==============================================
__device__ __forceinline__ uint32_t smem_u32(const void* p) {
    uint32_t a;
    asm("{ .reg .u64 t; cvta.to.shared.u64 t, %1; cvt.u32.u64 %0, t; }"
        : "=r"(a) : "l"(p));
    return a;
}
__device__ __forceinline__ void cp_async16(uint32_t dst, const void* src) {
    asm volatile("cp.async.cg.shared.global [%0], [%1], 16;"
                 :: "r"(dst), "l"(src) : "memory");
}
__device__ __forceinline__ void cp_commit() {
    asm volatile("cp.async.commit_group;" ::: "memory");
}
__device__ __forceinline__ void cp_wait1() {
    asm volatile("cp.async.wait_group 1;" ::: "memory");
}
__device__ __forceinline__ void cp_wait0() {
    asm volatile("cp.async.wait_group 0;" ::: "memory");
}
__device__ __forceinline__ void ldm_x4(uint32_t& r0, uint32_t& r1,
                                       uint32_t& r2, uint32_t& r3, uint32_t a) {
    asm volatile("ldmatrix.sync.aligned.m8n8.x4.shared.b16 {%0,%1,%2,%3}, [%4];"
                 : "=r"(r0), "=r"(r1), "=r"(r2), "=r"(r3) : "r"(a));
}
__device__ __forceinline__ void mma16816(float* d, const uint32_t* a, const uint32_t* b) {
    asm volatile(
        "mma.sync.aligned.m16n8k16.row.col.f32.bf16.bf16.f32 "
        "{%0,%1,%2,%3}, {%4,%5,%6,%7}, {%8,%9}, {%0,%1,%2,%3};"
        : "+f"(d[0]), "+f"(d[1]), "+f"(d[2]), "+f"(d[3])
        : "r"(a[0]), "r"(a[1]), "r"(a[2]), "r"(a[3]), "r"(b[0]), "r"(b[1]));
}
__device__ __forceinline__ uint32_t sw128(uint32_t o) { return o ^ ((o >> 3) & 0x70); }

// ===================== split fp32 -> (bf16 hi, bf16 lo) =====================
__global__ void split_kernel(const float* __restrict__ X, int n,
                             bf16* __restrict__ hi, bf16* __restrict__ lo)
{
    const int i = blockIdx.x * blockDim.x + threadIdx.x;
    if (i >= n) return;
    const float a = X[i];
    const bf16 h = __float2bfloat16(a);
    hi[i] = h;
    lo[i] = __float2bfloat16(a - __bfloat162float(h));
}

// ===================== generic HMMA split GEMM ==============================
#define STG_BYTES 65536
#define OFF_AH    0
#define OFF_AL    16384
#define OFF_BH    32768
#define OFF_BL    49152

template<int ACT, bool ADD_C, bool WSPLIT>
__global__ __launch_bounds__(256)
void hgemm_nt(const bf16* __restrict__ Ah, const bf16* __restrict__ Al,
              const bf16* __restrict__ Bh, const bf16* __restrict__ Bl,
              const float* __restrict__ bias, float* __restrict__ C,
              bf16* __restrict__ Sh, bf16* __restrict__ Sl,
              float salpha, int N, int K)
{
    extern __shared__ char smem[];
    const uint32_t sb = smem_u32(smem);
    const int tid = threadIdx.x;
    const int w = tid >> 5, l = tid & 31;
    const int m0 = (w & 1) * 64;
    const int n0 = (w >> 1) * 32;
    const int arow0 = blockIdx.y * 128;
    const int brow0 = blockIdx.x * 128;

    const int g  = l >> 3, lr = l & 7;
    const int ar  = (g & 1) * 8 + lr;
    const int acb = (g >> 1) * 16;
    const int br  = (g >> 1) * 8 + lr;
    const int bcb = (g & 1) * 16;

    float acc[4][4][4];
#pragma unroll
    for (int i = 0; i < 4; i++)
#pragma unroll
        for (int j = 0; j < 4; j++)
#pragma unroll
            for (int q = 0; q < 4; q++) acc[i][j][q] = 0.0f;

    auto load_stage = [&](int kc, int s) {
        const uint32_t base = sb + s * STG_BYTES;
        const int kof = kc * 64;
#pragma unroll
        for (int i = 0; i < 4; i++) {
            const int v = tid + i * 256;
            const int r = v >> 3;
            const int cb = (v & 7) * 16;
            const uint32_t sw = sw128((uint32_t)(r * 128 + cb));
            const size_t ga = (size_t)(arow0 + r) * K + kof + (v & 7) * 8;
            const size_t gb = (size_t)(brow0 + r) * K + kof + (v & 7) * 8;
            cp_async16(base + OFF_AH + sw, Ah + ga);
            cp_async16(base + OFF_AL + sw, Al + ga);
            cp_async16(base + OFF_BH + sw, Bh + gb);
            cp_async16(base + OFF_BL + sw, Bl + gb);
        }
        cp_commit();
    };

    const int NKC = K >> 6;
    load_stage(0, 0);

    for (int kc = 0; kc < NKC; kc++) {
        if (kc + 1 < NKC) { load_stage(kc + 1, (kc + 1) & 1); cp_wait1(); }
        else              { cp_wait0(); }
        __syncthreads();

        const uint32_t base = sb + (kc & 1) * STG_BYTES;
#pragma unroll
        for (int ks = 0; ks < 4; ks++) {
            const int kb = ks * 32;
            uint32_t fah[4][4], fal[4][4];
#pragma unroll
            for (int mf = 0; mf < 4; mf++) {
                const uint32_t ro = (uint32_t)((m0 + mf * 16 + ar) * 128 + kb + acb);
                ldm_x4(fah[mf][0], fah[mf][1], fah[mf][2], fah[mf][3],
                       base + OFF_AH + sw128(ro));
                ldm_x4(fal[mf][0], fal[mf][1], fal[mf][2], fal[mf][3],
                       base + OFF_AL + sw128(ro));
            }
            uint32_t fbh[4][2], fbl[4][2];
#pragma unroll
            for (int np = 0; np < 2; np++) {
                const uint32_t ro = (uint32_t)((n0 + np * 16 + br) * 128 + kb + bcb);
                uint32_t r0, r1, r2, r3;
                ldm_x4(r0, r1, r2, r3, base + OFF_BH + sw128(ro));
                fbh[np * 2 + 0][0] = r0; fbh[np * 2 + 0][1] = r1;
                fbh[np * 2 + 1][0] = r2; fbh[np * 2 + 1][1] = r3;
                ldm_x4(r0, r1, r2, r3, base + OFF_BL + sw128(ro));
                fbl[np * 2 + 0][0] = r0; fbl[np * 2 + 0][1] = r1;
                fbl[np * 2 + 1][0] = r2; fbl[np * 2 + 1][1] = r3;
            }
#pragma unroll
            for (int mf = 0; mf < 4; mf++)
#pragma unroll
                for (int nf = 0; nf < 4; nf++) {
                    mma16816(acc[mf][nf], fah[mf], fbh[nf]);
                    mma16816(acc[mf][nf], fah[mf], fbl[nf]);
                    mma16816(acc[mf][nf], fal[mf], fbh[nf]);
                }
        }
        __syncthreads();
    }

    const int qr = l >> 2, qc = (l & 3) * 2;
#pragma unroll
    for (int mf = 0; mf < 4; mf++) {
#pragma unroll
        for (int nf = 0; nf < 4; nf++) {
            const int col = brow0 + n0 + nf * 8 + qc;
            const float b0 = bias ? bias[col] : 0.0f;
            const float b1 = bias ? bias[col + 1] : 0.0f;
#pragma unroll
            for (int half = 0; half < 2; half++) {
                const int row = arow0 + m0 + mf * 16 + qr + half * 8;
                float v0 = acc[mf][nf][half * 2 + 0] + b0;
                float v1 = acc[mf][nf][half * 2 + 1] + b1;
                if (ACT == 1) {
                    v0 = v0 > 0.0f ? v0 : 0.01f * v0;
                    v1 = v1 > 0.0f ? v1 : 0.01f * v1;
                }
                const size_t o = (size_t)row * N + col;
                if (ADD_C) {
                    float2 old = *(float2*)(C + o);
                    v0 += old.x; v1 += old.y;
                }
                *(float2*)(C + o) = make_float2(v0, v1);
                if (WSPLIT) {
                    const float s0 = v0 * salpha, s1 = v1 * salpha;
                    const bf16 h0 = __float2bfloat16(s0);
                    const bf16 h1 = __float2bfloat16(s1);
                    Sh[o]     = h0;
                    Sh[o + 1] = h1;
                    Sl[o]     = __float2bfloat16(s0 - __bfloat162float(h0));
                    Sl[o + 1] = __float2bfloat16(s1 - __bfloat162float(h1));
                }
            }
        }
    }
}

// ===================== HMMA attn GEMM + fused per-tile top-6 ================
// Computes 128x128 tile of S = A@B^T (3-term split), stages it in smem, and
// writes per-row top-6 (val,idx) partials. S never touches global memory.
#define EPI_STRIDE 132                       // floats per staged row (pad)
#define EPI_MV     69632                     // byte offset of merge vals
#define EPI_MI     (EPI_MV + 6144)           // byte offset of merge idxs

__global__ __launch_bounds__(256)
void attn_hmma_topk_kernel(const bf16* __restrict__ Ah, const bf16* __restrict__ Al,
                           const bf16* __restrict__ Bh, const bf16* __restrict__ Bl,
                           float* __restrict__ PV, int* __restrict__ PIx)
{
    extern __shared__ char smem[];
    const uint32_t sb = smem_u32(smem);
    const int tid = threadIdx.x;
    const int w = tid >> 5, l = tid & 31;
    const int m0 = (w & 1) * 64;
    const int n0 = (w >> 1) * 32;
    const int arow0 = blockIdx.y * 128;
    const int brow0 = blockIdx.x * 128;

    const int g  = l >> 3, lr = l & 7;
    const int ar  = (g & 1) * 8 + lr;
    const int acb = (g >> 1) * 16;
    const int br  = (g >> 1) * 8 + lr;
    const int bcb = (g & 1) * 16;

    float acc[4][4][4];
#pragma unroll
    for (int i = 0; i < 4; i++)
#pragma unroll
        for (int j = 0; j < 4; j++)
#pragma unroll
            for (int q = 0; q < 4; q++) acc[i][j][q] = 0.0f;

    auto load_stage = [&](int kc, int s) {
        const uint32_t base = sb + s * STG_BYTES;
        const int kof = kc * 64;
#pragma unroll
        for (int i = 0; i < 4; i++) {
            const int v = tid + i * 256;
            const int r = v >> 3;
            const int cb = (v & 7) * 16;
            const uint32_t sw = sw128((uint32_t)(r * 128 + cb));
            const size_t ga = (size_t)(arow0 + r) * En + kof + (v & 7) * 8;
            const size_t gb = (size_t)(brow0 + r) * En + kof + (v & 7) * 8;
            cp_async16(base + OFF_AH + sw, Ah + ga);
            cp_async16(base + OFF_AL + sw, Al + ga);
            cp_async16(base + OFF_BH + sw, Bh + gb);
            cp_async16(base + OFF_BL + sw, Bl + gb);
        }
        cp_commit();
    };

    load_stage(0, 0);
    const int NKC = En / 64;
    for (int kc = 0; kc < NKC; kc++) {
        if (kc + 1 < NKC) { load_stage(kc + 1, (kc + 1) & 1); cp_wait1(); }
        else              { cp_wait0(); }
        __syncthreads();

        const uint32_t base = sb + (kc & 1) * STG_BYTES;
#pragma unroll
        for (int ks = 0; ks < 4; ks++) {
            const int kb = ks * 32;
            uint32_t fah[4][4], fal[4][4];
#pragma unroll
            for (int mf = 0; mf < 4; mf++) {
                const uint32_t ro = (uint32_t)((m0 + mf * 16 + ar) * 128 + kb + acb);
                ldm_x4(fah[mf][0], fah[mf][1], fah[mf][2], fah[mf][3],
                       base + OFF_AH + sw128(ro));
                ldm_x4(fal[mf][0], fal[mf][1], fal[mf][2], fal[mf][3],
                       base + OFF_AL + sw128(ro));
            }
            uint32_t fbh[4][2], fbl[4][2];
#pragma unroll
            for (int np = 0; np < 2; np++) {
                const uint32_t ro = (uint32_t)((n0 + np * 16 + br) * 128 + kb + bcb);
                uint32_t r0, r1, r2, r3;
                ldm_x4(r0, r1, r2, r3, base + OFF_BH + sw128(ro));
                fbh[np * 2 + 0][0] = r0; fbh[np * 2 + 0][1] = r1;
                fbh[np * 2 + 1][0] = r2; fbh[np * 2 + 1][1] = r3;
                ldm_x4(r0, r1, r2, r3, base + OFF_BL + sw128(ro));
                fbl[np * 2 + 0][0] = r0; fbl[np * 2 + 0][1] = r1;
                fbl[np * 2 + 1][0] = r2; fbl[np * 2 + 1][1] = r3;
            }
#pragma unroll
            for (int mf = 0; mf < 4; mf++)
#pragma unroll
                for (int nf = 0; nf < 4; nf++) {
                    mma16816(acc[mf][nf], fah[mf], fbh[nf]);
                    mma16816(acc[mf][nf], fah[mf], fbl[nf]);
                    mma16816(acc[mf][nf], fal[mf], fbh[nf]);
                }
        }
        __syncthreads();
    }

    // ---- stage fp32 tile into (now dead) pipeline smem ----
    float* st = (float*)smem;
    const int qr = l >> 2, qc = (l & 3) * 2;
#pragma unroll
    for (int mf = 0; mf < 4; mf++) {
#pragma unroll
        for (int nf = 0; nf < 4; nf++) {
            const int col = n0 + nf * 8 + qc;
#pragma unroll
            for (int half = 0; half < 2; half++) {
                const int row = m0 + mf * 16 + qr + half * 8;
                *(float2*)(st + row * EPI_STRIDE + col) =
                    make_float2(acc[mf][nf][half * 2 + 0], acc[mf][nf][half * 2 + 1]);
            }
        }
    }
    __syncthreads();

    // ---- per-row top-6: thread t handles row t/2, half t&1 (64 cols) ----
    const int r = tid >> 1;
    const int h = tid & 1;
    float lv[TKn]; int li[TKn];
#pragma unroll
    for (int k = 0; k < TKn; k++) { lv[k] = -INFINITY; li[k] = 0x7fffffff; }
    const float* rowp = st + r * EPI_STRIDE + h * 64;
    const int cbase = brow0 + h * 64;
#pragma unroll 4
    for (int j = 0; j < 64; j++) {
        const float v = rowp[j];
        if (v > lv[TKn - 1]) {
            lv[TKn - 1] = v; li[TKn - 1] = cbase + j;
#pragma unroll
            for (int k = TKn - 1; k > 0; k--) {
                bool up = (lv[k] > lv[k - 1]) ||
                          (lv[k] == lv[k - 1] && li[k] < li[k - 1]);
                if (up) {
                    float tv = lv[k]; lv[k] = lv[k - 1]; lv[k - 1] = tv;
                    int   ti = li[k]; li[k] = li[k - 1]; li[k - 1] = ti;
                }
            }
        }
    }
    // merge halves via smem
    float* mv = (float*)(smem + EPI_MV);
    int*   mi = (int*)  (smem + EPI_MI);
#pragma unroll
    for (int k = 0; k < TKn; k++) { mv[tid * TKn + k] = lv[k]; mi[tid * TKn + k] = li[k]; }
    __syncthreads();
    if (h == 0) {
        const float* ov = mv + (tid + 1) * TKn;
        const int*   oi = mi + (tid + 1) * TKn;
        float fv[TKn]; int fi[TKn];
        int i1 = 0, i2 = 0;
#pragma unroll
        for (int k = 0; k < TKn; k++) {
            bool take1 = (lv[i1] > ov[i2]) || (lv[i1] == ov[i2] && li[i1] < oi[i2]);
            if (take1) { fv[k] = lv[i1]; fi[k] = li[i1]; i1++; }
            else       { fv[k] = ov[i2]; fi[k] = oi[i2]; i2++; }
        }
        const size_t o = ((size_t)blockIdx.x * Mn + (arow0 + r)) * TKn;
#pragma unroll
        for (int k = 0; k < TKn; k++) { PV[o + k] = fv[k]; PIx[o + k] = fi[k]; }
    }
}

// ---- merge 64 per-tile top-6 lists -> global top-6 per row -----------------
__global__ __launch_bounds__(64)
void topk_merge_kernel(const float* __restrict__ PV, const int* __restrict__ PIx,
                       float* __restrict__ tkv, int* __restrict__ tki)
{
    const int row = blockIdx.x;
    const int t = threadIdx.x;              // 0..63 = tile id
    float v[TKn]; int id[TKn];
    const size_t o = ((size_t)t * Mn + row) * TKn;
#pragma unroll
    for (int k = 0; k < TKn; k++) { v[k] = PV[o + k]; id[k] = PIx[o + k]; }

    __shared__ float rv[64];
    __shared__ int   ri[64];
    __shared__ int   rt[64];
    __shared__ int   win;
    int ptr = 0;
    for (int sel = 0; sel < TKn; sel++) {
        rv[t] = v[ptr]; ri[t] = id[ptr]; rt[t] = t;   // ptr < 6 always (6 sels)
        __syncthreads();
        for (int s = 32; s > 0; s >>= 1) {
            if (t < s) {
                float v2 = rv[t + s]; int i2 = ri[t + s];
                if (v2 > rv[t] || (v2 == rv[t] && i2 < ri[t])) {
                    rv[t] = v2; ri[t] = i2; rt[t] = rt[t + s];
                }
            }
            __syncthreads();
        }
        if (t == 0) {
            tkv[row * TKn + sel] = rv[0];
            tki[row * TKn + sel] = ri[0];
            win = rt[0];
        }
        __syncthreads();
        if (t == win && ptr < TKn - 1) ptr++;
        __syncthreads();
    }
}

// ---- column partial reduce (optionally row-weighted) -----------------------
template<bool W>
__global__ void colred_kernel(const float* __restrict__ X,
                              const float* __restrict__ wgt,
                              float* __restrict__ part, int rows, int cols)
{
    const int col   = blockIdx.x * blockDim.x + threadIdx.x;
    const int chunk = blockIdx.y;
    const int rpc   = rows / gridDim.y;
    const int r0    = chunk * rpc;
    float s = 0.0f;
    for (int r = r0; r < r0 + rpc; r++) {
        float v = X[(size_t)r * cols + col];
        if (W) v *= wgt[r];
        s += v;
    }
    part[chunk * cols + col] = s;
}

__global__ void cmfin_kernel(const float* __restrict__ part, float* __restrict__ cm)
{
    const int e = threadIdx.x;
    float s = 0.0f;
    for (int c = 0; c < 256; c++) s += part[c * En + e];
    cm[e] = s * (1.0f / (float)Mn);
}

// ---- h = (h + colmean)*0.5, write bf16 split (vectorized) -------------------
__global__ void meanscale_split_kernel(const float* __restrict__ H,
                                       const float* __restrict__ cm,
                                       bf16* __restrict__ hh, bf16* __restrict__ hl)
{
    const int i4 = (blockIdx.x * blockDim.x + threadIdx.x) * 4;
    const int e = i4 & (En - 1);
    const float4 hv = *(const float4*)(H + i4);
    const float4 cv = *(const float4*)(cm + e);
    float v[4] = { (hv.x + cv.x) * 0.5f, (hv.y + cv.y) * 0.5f,
                   (hv.z + cv.z) * 0.5f, (hv.w + cv.w) * 0.5f };
    bf16 hi[4], lo[4];
#pragma unroll
    for (int k = 0; k < 4; k++) {
        hi[k] = __float2bfloat16(v[k]);
        lo[k] = __float2bfloat16(v[k] - __bfloat162float(hi[k]));
    }
    *(__nv_bfloat162*)(hh + i4)     = __nv_bfloat162(hi[0], hi[1]);
    *(__nv_bfloat162*)(hh + i4 + 2) = __nv_bfloat162(hi[2], hi[3]);
    *(__nv_bfloat162*)(hl + i4)     = __nv_bfloat162(lo[0], lo[1]);
    *(__nv_bfloat162*)(hl + i4 + 2) = __nv_bfloat162(lo[2], lo[3]);
}

// ---- per-row combine; writes U,V as bf16 splits -----------------------------
__global__ __launch_bounds__(256)
void combine_kernel(const float* __restrict__ EH, const float* __restrict__ ET,
                    const float* __restrict__ tkv, const int* __restrict__ tki,
                    bf16* __restrict__ Uh, bf16* __restrict__ Ul,
                    bf16* __restrict__ Vh, bf16* __restrict__ Vl)
{
    const int row = blockIdx.x;
    const int tid = threadIdx.x;

    __shared__ float sh_eh[En];
    __shared__ float sh_nb[TKn][En];
    __shared__ float w[TKn]; __shared__ int idx[TKn];
    __shared__ float p[TKn]; __shared__ float q[TKn];
    __shared__ float snb[TKn], sg[TKn];
    __shared__ float red[256];

    if (tid < TKn) { w[tid] = tkv[row * TKn + tid]; idx[tid] = tki[row * TKn + tid]; }
    __syncthreads();

    for (int e = tid; e < En; e += 256) sh_eh[e] = EH[(size_t)row * En + e];
#pragma unroll
    for (int k = 0; k < TKn; k++) {
        const float* src = ET + (size_t)idx[k] * En;
        for (int e = tid; e < En; e += 256) sh_nb[k][e] = src[e];
    }
    if (tid == 0) {
        float mx = w[0];
        for (int k = 1; k < TKn; k++) mx = fmaxf(mx, w[k]);
        float s = 0.0f;
        for (int k = 0; k < TKn; k++) { p[k] = expf(w[k] - mx); s += p[k]; }
        float inv = 1.0f / s;
        for (int k = 0; k < TKn; k++) p[k] *= inv;
    }
    __syncthreads();

    float pn[TKn], pg[TKn];
#pragma unroll
    for (int k = 0; k < TKn; k++) { pn[k] = 0.0f; pg[k] = 0.0f; }
    for (int e = tid; e < En; e += 256) {
        const float eh = sh_eh[e];
#pragma unroll
        for (int k = 0; k < TKn; k++) {
            const float nb = sh_nb[k][e];
            pn[k] += nb;
            pg[k] += tanhf((2.0f - p[k]) * eh + p[k] * nb);
        }
    }
#pragma unroll
    for (int k = 0; k < TKn; k++) {
        red[tid] = pn[k]; __syncthreads();
        for (int s = 128; s > 0; s >>= 1) { if (tid < s) red[tid] += red[tid + s]; __syncthreads(); }
        if (tid == 0) snb[k] = red[0];
        __syncthreads();
        red[tid] = pg[k]; __syncthreads();
        for (int s = 128; s > 0; s >>= 1) { if (tid < s) red[tid] += red[tid + s]; __syncthreads(); }
        if (tid == 0) sg[k] = red[0];
        __syncthreads();
    }
    if (tid == 0) {
        float ka[TKn];
        float mx = -INFINITY;
        for (int k = 0; k < TKn; k++) { ka[k] = snb[k] * sg[k]; mx = fmaxf(mx, ka[k]); }
        float s = 0.0f;
        for (int k = 0; k < TKn; k++) { q[k] = expf(ka[k] - mx); s += q[k]; }
        float inv = 1.0f / s;
        for (int k = 0; k < TKn; k++) q[k] *= inv;
    }
    __syncthreads();

    for (int e = tid; e < En; e += 256) {
        float en = 0.0f;
#pragma unroll
        for (int k = 0; k < TKn; k++) en = fmaf(q[k], sh_nb[k][e], en);
        const float eh = sh_eh[e];
        const size_t o = (size_t)row * En + e;
        const float u = eh + en, v = eh * en;
        const bf16 uh = __float2bfloat16(u);
        const bf16 vh = __float2bfloat16(v);
        Uh[o] = uh; Ul[o] = __float2bfloat16(u - __bfloat162float(uh));
        Vh[o] = vh; Vl[o] = __float2bfloat16(v - __bfloat162float(vh));
    }
}

// ---- g = G1 @ a2_w^T + a2_b -------------------------------------------------
__global__ void matvec_kernel(const float* __restrict__ G1,
                              const float* __restrict__ a2w,
                              const float* __restrict__ a2b,
                              float* __restrict__ gv)
{
    const int warp = (blockIdx.x * blockDim.x + threadIdx.x) >> 5;
    const int lane = threadIdx.x & 31;
    if (warp >= Mn) return;
    const float* rowp = G1 + (size_t)warp * (En / 2);
    float s = 0.0f;
    for (int j = lane; j < En / 2; j += 32) s = fmaf(rowp[j], a2w[j], s);
#pragma unroll
    for (int o = 16; o > 0; o >>= 1) s += __shfl_xor_sync(0xffffffffu, s, o);
    if (lane == 0) gv[warp] = s + a2b[0];
}

__global__ void softmax_att_kernel(const float* __restrict__ gv, float* __restrict__ att)
{
    __shared__ float red[256];
    const int tid = threadIdx.x;
    float mx = -INFINITY;
    for (int i = tid; i < Mn; i += 256) mx = fmaxf(mx, gv[i]);
    red[tid] = mx; __syncthreads();
    for (int s = 128; s > 0; s >>= 1) { if (tid < s) red[tid] = fmaxf(red[tid], red[tid + s]); __syncthreads(); }
    mx = red[0]; __syncthreads();
    float se = 0.0f;
    for (int i = tid; i < Mn; i += 256) se += expf(gv[i] - mx);
    red[tid] = se; __syncthreads();
    for (int s = 128; s > 0; s >>= 1) { if (tid < s) red[tid] += red[tid + s]; __syncthreads(); }
    const float inv = 1.0f / red[0];
    for (int i = tid; i < Mn; i += 256) att[i] = expf(gv[i] - mx) * inv;
}

__global__ void pool_ln_kernel(const float* __restrict__ part,
                               const float* __restrict__ g,
                               const float* __restrict__ b,
                               float* __restrict__ out)
{
    __shared__ float red[En];
    const int e = threadIdx.x;
    float s = 0.0f;
    for (int c = 0; c < 256; c++) s += part[c * En + e];
    red[e] = s; __syncthreads();
    for (int st = 256; st > 0; st >>= 1) { if (e < st) red[e] += red[e + st]; __syncthreads(); }
    const float mu = red[0] * (1.0f / (float)En);
    __syncthreads();
    const float d = s - mu;
    red[e] = d * d; __syncthreads();
    for (int st = 256; st > 0; st >>= 1) { if (e < st) red[e] += red[e + st]; __syncthreads(); }
    const float var = red[0] * (1.0f / (float)En);
    out[e] = d * rsqrtf(var + 1e-5f) * g[e] + b[e];
}

// --------------------------------------------------------------------------
extern "C" void kernel_launch(void* const* d_in, const int* in_sizes, int n_in,
                              void* d_out, int out_size)
{
    (void)in_sizes; (void)n_in; (void)out_size;
    const float* x    = (const float*)d_in[0];
    const float* fc1w = (const float*)d_in[1];
    const float* fc1b = (const float*)d_in[2];
    const float* whw  = (const float*)d_in[3];
    const float* whb  = (const float*)d_in[4];
    const float* wtw  = (const float*)d_in[5];
    const float* wtb  = (const float*)d_in[6];
    const float* l1w  = (const float*)d_in[7];
    const float* l1b  = (const float*)d_in[8];
    const float* l2w  = (const float*)d_in[9];
    const float* l2b  = (const float*)d_in[10];
    const float* a1w  = (const float*)d_in[11];
    const float* a1b  = (const float*)d_in[12];
    const float* a2w  = (const float*)d_in[13];
    const float* a2b  = (const float*)d_in[14];
    const float* lng  = (const float*)d_in[15];
    const float* lnb  = (const float*)d_in[16];
    float* out = (float*)d_out;

    float *H, *EH, *ET, *PV, *TKV, *EMB, *G1, *GV, *ATT, *PART, *CM;
    bf16 *AH, *AL, *BH, *BL, *XH, *XL, *HH, *HL, *UH, *UL, *VH, *VL, *MH, *ML, *WH, *WL;
    int *TKI, *PIx;
    cudaGetSymbolAddress((void**)&H,   g_H);
    cudaGetSymbolAddress((void**)&EH,  g_EH);
    cudaGetSymbolAddress((void**)&ET,  g_ET);
    cudaGetSymbolAddress((void**)&PV,  g_PV);
    cudaGetSymbolAddress((void**)&PIx, g_PIx);
    cudaGetSymbolAddress((void**)&AH,  g_AH);
    cudaGetSymbolAddress((void**)&AL,  g_AL);
    cudaGetSymbolAddress((void**)&BH,  g_BH);
    cudaGetSymbolAddress((void**)&BL,  g_BL);
    cudaGetSymbolAddress((void**)&XH,  g_XH);
    cudaGetSymbolAddress((void**)&XL,  g_XL);
    cudaGetSymbolAddress((void**)&HH,  g_HH);
    cudaGetSymbolAddress((void**)&HL,  g_HL);
    cudaGetSymbolAddress((void**)&UH,  g_UH);
    cudaGetSymbolAddress((void**)&UL,  g_UL);
    cudaGetSymbolAddress((void**)&VH,  g_VH);
    cudaGetSymbolAddress((void**)&VL,  g_VL);
    cudaGetSymbolAddress((void**)&MH,  g_MH);
    cudaGetSymbolAddress((void**)&ML,  g_ML);
    cudaGetSymbolAddress((void**)&WH,  g_WH);
    cudaGetSymbolAddress((void**)&WL,  g_WL);
    cudaGetSymbolAddress((void**)&TKV, g_TKV);
    cudaGetSymbolAddress((void**)&TKI, g_TKI);
    cudaGetSymbolAddress((void**)&EMB, g_EMB);
    cudaGetSymbolAddress((void**)&G1,  g_G1);
    cudaGetSymbolAddress((void**)&GV,  g_GV);
    cudaGetSymbolAddress((void**)&ATT, g_ATT);
    cudaGetSymbolAddress((void**)&PART,g_PART);
    cudaGetSymbolAddress((void**)&CM,  g_CM);

    const float scale = 1.0f / sqrtf((float)En);

    cudaFuncSetAttribute(hgemm_nt<1, false, false>, cudaFuncAttributeMaxDynamicSharedMemorySize, 2 * STG_BYTES);
    cudaFuncSetAttribute(hgemm_nt<0, false, true >, cudaFuncAttributeMaxDynamicSharedMemorySize, 2 * STG_BYTES);
    cudaFuncSetAttribute(hgemm_nt<1, true,  true >, cudaFuncAttributeMaxDynamicSharedMemorySize, 2 * STG_BYTES);
    cudaFuncSetAttribute(attn_hmma_topk_kernel, cudaFuncAttributeMaxDynamicSharedMemorySize, 2 * STG_BYTES);

    // 1) h = lrelu(x @ fc1^T + b)
    split_kernel<<<(Mn * INn + 255) / 256, 256>>>(x, Mn * INn, XH, XL);
    split_kernel<<<(En * INn + 255) / 256, 256>>>(fc1w, En * INn, WH, WL);
    hgemm_nt<1, false, false><<<dim3(En / 128, Mn / 128), 256, 2 * STG_BYTES>>>(
        XH, XL, WH, WL, fc1b, H, nullptr, nullptr, 0.0f, En, INn);
    // 2) h = (h + colmean(h)) * 0.5  -> split
    colred_kernel<false><<<dim3(En / 128, 256), 128>>>(H, nullptr, PART, Mn, En);
    cmfin_kernel<<<1, En>>>(PART, CM);
    meanscale_split_kernel<<<(Mn * En) / 1024, 256>>>(H, CM, HH, HL);
    // 3) e_h (emits scaled split = attn A), e_t (emits split = attn B)
    split_kernel<<<(En * En + 255) / 256, 256>>>(whw, En * En, WH, WL);
    hgemm_nt<0, false, true><<<dim3(En / 128, Mn / 128), 256, 2 * STG_BYTES>>>(
        HH, HL, WH, WL, whb, EH, AH, AL, scale, En, En);
    split_kernel<<<(En * En + 255) / 256, 256>>>(wtw, En * En, WH, WL);
    hgemm_nt<0, false, true><<<dim3(En / 128, Mn / 128), 256, 2 * STG_BYTES>>>(
        HH, HL, WH, WL, wtb, ET, BH, BL, 1.0f, En, En);
    // 4+5) S tile + fused per-tile top-6, then merge
    attn_hmma_topk_kernel<<<dim3(NTILE, NTILE), 256, 2 * STG_BYTES>>>(AH, AL, BH, BL, PV, PIx);
    topk_merge_kernel<<<Mn, 64>>>(PV, PIx, TKV, TKI);
    // 6) combine -> U, V bf16 splits
    combine_kernel<<<Mn, 256>>>(EH, ET, TKV, TKI, UH, UL, VH, VL);
    // 7) emb = lrelu(U@l1^T+b) + lrelu(V@l2^T+b)
    split_kernel<<<(En * En + 255) / 256, 256>>>(l1w, En * En, WH, WL);
    hgemm_nt<1, false, false><<<dim3(En / 128, Mn / 128), 256, 2 * STG_BYTES>>>(
        UH, UL, WH, WL, l1b, EMB, nullptr, nullptr, 0.0f, En, En);
    split_kernel<<<(En * En + 255) / 256, 256>>>(l2w, En * En, WH, WL);
    hgemm_nt<1, true, true><<<dim3(En / 128, Mn / 128), 256, 2 * STG_BYTES>>>(
        VH, VL, WH, WL, l2b, EMB, MH, ML, 1.0f, En, En);
    // 8) readout gate
    split_kernel<<<((En / 2) * En + 255) / 256, 256>>>(a1w, (En / 2) * En, WH, WL);
    hgemm_nt<1, false, false><<<dim3((En / 2) / 128, Mn / 128), 256, 2 * STG_BYTES>>>(
        MH, ML, WH, WL, a1b, G1, nullptr, nullptr, 0.0f, En / 2, En);
    matvec_kernel<<<Mn / 8, 256>>>(G1, a2w, a2b, GV);
    // 9) softmax over nodes, weighted pool, layernorm
    softmax_att_kernel<<<1, 256>>>(GV, ATT);
    colred_kernel<true><<<dim3(En / 128, 256), 128>>>(EMB, ATT, PART, Mn, En);
    pool_ln_kernel<<<1, En>>>(PART, lng, lnb, out);
}

// round 6
// speedup vs baseline: 1.4305x; 1.4305x over previous
#include <cuda_runtime.h>
#include <cuda_bf16.h>
#include <math.h>
#include <stdint.h>

#define Mn  8192
#define En  512
#define INn 384
#define TKn 6

typedef __nv_bfloat16 bf16;

// ------------------------- scratch (__device__ globals; no allocation) -----
__device__ float g_H  [Mn * En];
__device__ float g_EH [Mn * En];
__device__ float g_ET [Mn * En];
__device__ float g_S  [(size_t)Mn * Mn];
__device__ bf16  g_AH[Mn * En];
__device__ bf16  g_AL[Mn * En];
__device__ bf16  g_BH[Mn * En];
__device__ bf16  g_BL[Mn * En];
__device__ bf16  g_XH[Mn * INn];
__device__ bf16  g_XL[Mn * INn];
__device__ bf16  g_HH[Mn * En];
__device__ bf16  g_HL[Mn * En];
__device__ bf16  g_UH[Mn * En];
__device__ bf16  g_UL[Mn * En];
__device__ bf16  g_VH[Mn * En];
__device__ bf16  g_VL[Mn * En];
__device__ bf16  g_MH[Mn * En];
__device__ bf16  g_ML[Mn * En];
__device__ bf16  g_WH[En * En];
__device__ bf16  g_WL[En * En];
__device__ float g_TKV[Mn * TKn];
__device__ int   g_TKI[Mn * TKn];
__device__ float g_EMB[Mn * En];
__device__ float g_G1 [Mn * (En / 2)];
__device__ float g_GV [Mn];
__device__ float g_ATT[Mn];
__device__ float g_PART[256 * En];
__device__ float g_CM [En];

// ===================== helpers ==============================================
__device__ __forceinline__ uint32_t smem_u32(const void* p) {
    uint32_t a;
    asm("{ .reg .u64 t; cvta.to.shared.u64 t, %1; cvt.u32.u64 %0, t; }"
        : "=r"(a) : "l"(p));
    return a;
}
__device__ __forceinline__ void cp_async16(uint32_t dst, const void* src) {
    asm volatile("cp.async.cg.shared.global [%0], [%1], 16;"
                 :: "r"(dst), "l"(src) : "memory");
}
__device__ __forceinline__ void cp_commit() {
    asm volatile("cp.async.commit_group;" ::: "memory");
}
__device__ __forceinline__ void cp_wait1() {
    asm volatile("cp.async.wait_group 1;" ::: "memory");
}
__device__ __forceinline__ void cp_wait0() {
    asm volatile("cp.async.wait_group 0;" ::: "memory");
}
__device__ __forceinline__ void ldm_x4(uint32_t& r0, uint32_t& r1,
                                       uint32_t& r2, uint32_t& r3, uint32_t a) {
    asm volatile("ldmatrix.sync.aligned.m8n8.x4.shared.b16 {%0,%1,%2,%3}, [%4];"
                 : "=r"(r0), "=r"(r1), "=r"(r2), "=r"(r3) : "r"(a));
}
__device__ __forceinline__ void mma16816(float* d, const uint32_t* a, const uint32_t* b) {
    asm volatile(
        "mma.sync.aligned.m16n8k16.row.col.f32.bf16.bf16.f32 "
        "{%0,%1,%2,%3}, {%4,%5,%6,%7}, {%8,%9}, {%0,%1,%2,%3};"
        : "+f"(d[0]), "+f"(d[1]), "+f"(d[2]), "+f"(d[3])
        : "r"(a[0]), "r"(a[1]), "r"(a[2]), "r"(a[3]), "r"(b[0]), "r"(b[1]));
}
__device__ __forceinline__ uint32_t sw128(uint32_t o) { return o ^ ((o >> 3) & 0x70); }

// ===================== split fp32 -> (bf16 hi, bf16 lo) =====================
__global__ void split_kernel(const float* __restrict__ X, int n,
                             bf16* __restrict__ hi, bf16* __restrict__ lo)
{
    const int i = blockIdx.x * blockDim.x + threadIdx.x;
    if (i >= n) return;
    const float a = X[i];
    const bf16 h = __float2bfloat16(a);
    hi[i] = h;
    lo[i] = __float2bfloat16(a - __bfloat162float(h));
}

// ===================== generic HMMA split GEMM ==============================
#define STG_BYTES 65536
#define OFF_AH    0
#define OFF_AL    16384
#define OFF_BH    32768
#define OFF_BL    49152

template<int ACT, bool ADD_C, bool WSPLIT>
__global__ __launch_bounds__(256)
void hgemm_nt(const bf16* __restrict__ Ah, const bf16* __restrict__ Al,
              const bf16* __restrict__ Bh, const bf16* __restrict__ Bl,
              const float* __restrict__ bias, float* __restrict__ C,
              bf16* __restrict__ Sh, bf16* __restrict__ Sl,
              float salpha, int N, int K)
{
    extern __shared__ char smem[];
    const uint32_t sb = smem_u32(smem);
    const int tid = threadIdx.x;
    const int w = tid >> 5, l = tid & 31;
    const int m0 = (w & 1) * 64;
    const int n0 = (w >> 1) * 32;
    const int arow0 = blockIdx.y * 128;
    const int brow0 = blockIdx.x * 128;

    const int g  = l >> 3, lr = l & 7;
    const int ar  = (g & 1) * 8 + lr;
    const int acb = (g >> 1) * 16;
    const int br  = (g >> 1) * 8 + lr;
    const int bcb = (g & 1) * 16;

    float acc[4][4][4];
#pragma unroll
    for (int i = 0; i < 4; i++)
#pragma unroll
        for (int j = 0; j < 4; j++)
#pragma unroll
            for (int q = 0; q < 4; q++) acc[i][j][q] = 0.0f;

    auto load_stage = [&](int kc, int s) {
        const uint32_t base = sb + s * STG_BYTES;
        const int kof = kc * 64;
#pragma unroll
        for (int i = 0; i < 4; i++) {
            const int v = tid + i * 256;
            const int r = v >> 3;
            const int cb = (v & 7) * 16;
            const uint32_t sw = sw128((uint32_t)(r * 128 + cb));
            const size_t ga = (size_t)(arow0 + r) * K + kof + (v & 7) * 8;
            const size_t gb = (size_t)(brow0 + r) * K + kof + (v & 7) * 8;
            cp_async16(base + OFF_AH + sw, Ah + ga);
            cp_async16(base + OFF_AL + sw, Al + ga);
            cp_async16(base + OFF_BH + sw, Bh + gb);
            cp_async16(base + OFF_BL + sw, Bl + gb);
        }
        cp_commit();
    };

    const int NKC = K >> 6;
    load_stage(0, 0);

    for (int kc = 0; kc < NKC; kc++) {
        if (kc + 1 < NKC) { load_stage(kc + 1, (kc + 1) & 1); cp_wait1(); }
        else              { cp_wait0(); }
        __syncthreads();

        const uint32_t base = sb + (kc & 1) * STG_BYTES;
#pragma unroll
        for (int ks = 0; ks < 4; ks++) {
            const int kb = ks * 32;
            uint32_t fah[4][4], fal[4][4];
#pragma unroll
            for (int mf = 0; mf < 4; mf++) {
                const uint32_t ro = (uint32_t)((m0 + mf * 16 + ar) * 128 + kb + acb);
                ldm_x4(fah[mf][0], fah[mf][1], fah[mf][2], fah[mf][3],
                       base + OFF_AH + sw128(ro));
                ldm_x4(fal[mf][0], fal[mf][1], fal[mf][2], fal[mf][3],
                       base + OFF_AL + sw128(ro));
            }
            uint32_t fbh[4][2], fbl[4][2];
#pragma unroll
            for (int np = 0; np < 2; np++) {
                const uint32_t ro = (uint32_t)((n0 + np * 16 + br) * 128 + kb + bcb);
                uint32_t r0, r1, r2, r3;
                ldm_x4(r0, r1, r2, r3, base + OFF_BH + sw128(ro));
                fbh[np * 2 + 0][0] = r0; fbh[np * 2 + 0][1] = r1;
                fbh[np * 2 + 1][0] = r2; fbh[np * 2 + 1][1] = r3;
                ldm_x4(r0, r1, r2, r3, base + OFF_BL + sw128(ro));
                fbl[np * 2 + 0][0] = r0; fbl[np * 2 + 0][1] = r1;
                fbl[np * 2 + 1][0] = r2; fbl[np * 2 + 1][1] = r3;
            }
#pragma unroll
            for (int mf = 0; mf < 4; mf++)
#pragma unroll
                for (int nf = 0; nf < 4; nf++) {
                    mma16816(acc[mf][nf], fah[mf], fbh[nf]);
                    mma16816(acc[mf][nf], fah[mf], fbl[nf]);
                    mma16816(acc[mf][nf], fal[mf], fbh[nf]);
                }
        }
        __syncthreads();
    }

    const int qr = l >> 2, qc = (l & 3) * 2;
#pragma unroll
    for (int mf = 0; mf < 4; mf++) {
#pragma unroll
        for (int nf = 0; nf < 4; nf++) {
            const int col = brow0 + n0 + nf * 8 + qc;
            const float b0 = bias ? bias[col] : 0.0f;
            const float b1 = bias ? bias[col + 1] : 0.0f;
#pragma unroll
            for (int half = 0; half < 2; half++) {
                const int row = arow0 + m0 + mf * 16 + qr + half * 8;
                float v0 = acc[mf][nf][half * 2 + 0] + b0;
                float v1 = acc[mf][nf][half * 2 + 1] + b1;
                if (ACT == 1) {
                    v0 = v0 > 0.0f ? v0 : 0.01f * v0;
                    v1 = v1 > 0.0f ? v1 : 0.01f * v1;
                }
                const size_t o = (size_t)row * N + col;
                if (ADD_C) {
                    float2 old = *(float2*)(C + o);
                    v0 += old.x; v1 += old.y;
                }
                *(float2*)(C + o) = make_float2(v0, v1);
                if (WSPLIT) {
                    const float s0 = v0 * salpha, s1 = v1 * salpha;
                    const bf16 h0 = __float2bfloat16(s0);
                    const bf16 h1 = __float2bfloat16(s1);
                    Sh[o]     = h0;
                    Sh[o + 1] = h1;
                    Sl[o]     = __float2bfloat16(s0 - __bfloat162float(h0));
                    Sl[o + 1] = __float2bfloat16(s1 - __bfloat162float(h1));
                }
            }
        }
    }
}

// ===================== HMMA attn GEMM: S = A @ B^T ==========================
__global__ __launch_bounds__(256)
void attn_hmma_kernel(const bf16* __restrict__ Ah, const bf16* __restrict__ Al,
                      const bf16* __restrict__ Bh, const bf16* __restrict__ Bl,
                      float* __restrict__ S)
{
    extern __shared__ char smem[];
    const uint32_t sb = smem_u32(smem);
    const int tid = threadIdx.x;
    const int w = tid >> 5, l = tid & 31;
    const int m0 = (w & 1) * 64;
    const int n0 = (w >> 1) * 32;
    const int arow0 = blockIdx.y * 128;
    const int brow0 = blockIdx.x * 128;

    const int g  = l >> 3, lr = l & 7;
    const int ar  = (g & 1) * 8 + lr;
    const int acb = (g >> 1) * 16;
    const int br  = (g >> 1) * 8 + lr;
    const int bcb = (g & 1) * 16;

    float acc[4][4][4];
#pragma unroll
    for (int i = 0; i < 4; i++)
#pragma unroll
        for (int j = 0; j < 4; j++)
#pragma unroll
            for (int q = 0; q < 4; q++) acc[i][j][q] = 0.0f;

    auto load_stage = [&](int kc, int s) {
        const uint32_t base = sb + s * STG_BYTES;
        const int kof = kc * 64;
#pragma unroll
        for (int i = 0; i < 4; i++) {
            const int v = tid + i * 256;
            const int r = v >> 3;
            const int cb = (v & 7) * 16;
            const uint32_t sw = sw128((uint32_t)(r * 128 + cb));
            const size_t ga = (size_t)(arow0 + r) * En + kof + (v & 7) * 8;
            const size_t gb = (size_t)(brow0 + r) * En + kof + (v & 7) * 8;
            cp_async16(base + OFF_AH + sw, Ah + ga);
            cp_async16(base + OFF_AL + sw, Al + ga);
            cp_async16(base + OFF_BH + sw, Bh + gb);
            cp_async16(base + OFF_BL + sw, Bl + gb);
        }
        cp_commit();
    };

    load_stage(0, 0);
    const int NKC = En / 64;
    for (int kc = 0; kc < NKC; kc++) {
        if (kc + 1 < NKC) { load_stage(kc + 1, (kc + 1) & 1); cp_wait1(); }
        else              { cp_wait0(); }
        __syncthreads();

        const uint32_t base = sb + (kc & 1) * STG_BYTES;
#pragma unroll
        for (int ks = 0; ks < 4; ks++) {
            const int kb = ks * 32;
            uint32_t fah[4][4], fal[4][4];
#pragma unroll
            for (int mf = 0; mf < 4; mf++) {
                const uint32_t ro = (uint32_t)((m0 + mf * 16 + ar) * 128 + kb + acb);
                ldm_x4(fah[mf][0], fah[mf][1], fah[mf][2], fah[mf][3],
                       base + OFF_AH + sw128(ro));
                ldm_x4(fal[mf][0], fal[mf][1], fal[mf][2], fal[mf][3],
                       base + OFF_AL + sw128(ro));
            }
            uint32_t fbh[4][2], fbl[4][2];
#pragma unroll
            for (int np = 0; np < 2; np++) {
                const uint32_t ro = (uint32_t)((n0 + np * 16 + br) * 128 + kb + bcb);
                uint32_t r0, r1, r2, r3;
                ldm_x4(r0, r1, r2, r3, base + OFF_BH + sw128(ro));
                fbh[np * 2 + 0][0] = r0; fbh[np * 2 + 0][1] = r1;
                fbh[np * 2 + 1][0] = r2; fbh[np * 2 + 1][1] = r3;
                ldm_x4(r0, r1, r2, r3, base + OFF_BL + sw128(ro));
                fbl[np * 2 + 0][0] = r0; fbl[np * 2 + 0][1] = r1;
                fbl[np * 2 + 1][0] = r2; fbl[np * 2 + 1][1] = r3;
            }
#pragma unroll
            for (int mf = 0; mf < 4; mf++)
#pragma unroll
                for (int nf = 0; nf < 4; nf++) {
                    mma16816(acc[mf][nf], fah[mf], fbh[nf]);
                    mma16816(acc[mf][nf], fah[mf], fbl[nf]);
                    mma16816(acc[mf][nf], fal[mf], fbh[nf]);
                }
        }
        __syncthreads();
    }

    const int qr = l >> 2, qc = (l & 3) * 2;
#pragma unroll
    for (int mf = 0; mf < 4; mf++) {
        const int row = arow0 + m0 + mf * 16 + qr;
#pragma unroll
        for (int nf = 0; nf < 4; nf++) {
            const int col = brow0 + n0 + nf * 8 + qc;
            *(float2*)(S + (size_t)row * Mn + col) =
                make_float2(acc[mf][nf][0], acc[mf][nf][1]);
            *(float2*)(S + (size_t)(row + 8) * Mn + col) =
                make_float2(acc[mf][nf][2], acc[mf][nf][3]);
        }
    }
}

// ---- column partial reduce (optionally row-weighted) -----------------------
template<bool W>
__global__ void colred_kernel(const float* __restrict__ X,
                              const float* __restrict__ wgt,
                              float* __restrict__ part, int rows, int cols)
{
    const int col   = blockIdx.x * blockDim.x + threadIdx.x;
    const int chunk = blockIdx.y;
    const int rpc   = rows / gridDim.y;
    const int r0    = chunk * rpc;
    float s = 0.0f;
    for (int r = r0; r < r0 + rpc; r++) {
        float v = X[(size_t)r * cols + col];
        if (W) v *= wgt[r];
        s += v;
    }
    part[chunk * cols + col] = s;
}

__global__ void cmfin_kernel(const float* __restrict__ part, float* __restrict__ cm)
{
    const int e = threadIdx.x;
    float s = 0.0f;
    for (int c = 0; c < 256; c++) s += part[c * En + e];
    cm[e] = s * (1.0f / (float)Mn);
}

// ---- h = (h + colmean)*0.5, write bf16 split (vectorized) -------------------
__global__ void meanscale_split_kernel(const float* __restrict__ H,
                                       const float* __restrict__ cm,
                                       bf16* __restrict__ hh, bf16* __restrict__ hl)
{
    const int i4 = (blockIdx.x * blockDim.x + threadIdx.x) * 4;
    const int e = i4 & (En - 1);
    const float4 hv = *(const float4*)(H + i4);
    const float4 cv = *(const float4*)(cm + e);
    float v[4] = { (hv.x + cv.x) * 0.5f, (hv.y + cv.y) * 0.5f,
                   (hv.z + cv.z) * 0.5f, (hv.w + cv.w) * 0.5f };
    bf16 hi[4], lo[4];
#pragma unroll
    for (int k = 0; k < 4; k++) {
        hi[k] = __float2bfloat16(v[k]);
        lo[k] = __float2bfloat16(v[k] - __bfloat162float(hi[k]));
    }
    *(__nv_bfloat162*)(hh + i4)     = __nv_bfloat162(hi[0], hi[1]);
    *(__nv_bfloat162*)(hh + i4 + 2) = __nv_bfloat162(hi[2], hi[3]);
    *(__nv_bfloat162*)(hl + i4)     = __nv_bfloat162(lo[0], lo[1]);
    *(__nv_bfloat162*)(hl + i4 + 2) = __nv_bfloat162(lo[2], lo[3]);
}

// ---- per-row top-6 over S row (8192), float4 loads, jax tie-break -----------
__global__ __launch_bounds__(256)
void topk_kernel(const float* __restrict__ S,
                 float* __restrict__ tkv, int* __restrict__ tki)
{
    const int row = blockIdx.x;
    const int tid = threadIdx.x;
    const float* sr = S + (size_t)row * Mn;

    float lv[TKn]; int li[TKn];
#pragma unroll
    for (int k = 0; k < TKn; k++) { lv[k] = -INFINITY; li[k] = 0x7fffffff; }

    for (int j4 = tid * 4; j4 < Mn; j4 += 1024) {
        const float4 v4 = *(const float4*)(sr + j4);
        const float vs[4] = { v4.x, v4.y, v4.z, v4.w };
#pragma unroll
        for (int q = 0; q < 4; q++) {
            const float v = vs[q];
            if (v > lv[TKn - 1]) {
                lv[TKn - 1] = v; li[TKn - 1] = j4 + q;
#pragma unroll
                for (int k = TKn - 1; k > 0; k--) {
                    bool up = (lv[k] > lv[k - 1]) ||
                              (lv[k] == lv[k - 1] && li[k] < li[k - 1]);
                    if (up) {
                        float tv = lv[k]; lv[k] = lv[k - 1]; lv[k - 1] = tv;
                        int   ti = li[k]; li[k] = li[k - 1]; li[k - 1] = ti;
                    }
                }
            }
        }
    }

    __shared__ float sv[256 * TKn];
    __shared__ int   si[256 * TKn];
    __shared__ unsigned char sp[256];
    __shared__ float rv[256];
    __shared__ int   ri[256];
    __shared__ short rt[256];
#pragma unroll
    for (int k = 0; k < TKn; k++) { sv[tid * TKn + k] = lv[k]; si[tid * TKn + k] = li[k]; }
    sp[tid] = 0;
    __syncthreads();

    for (int sel = 0; sel < TKn; sel++) {
        const int pp = sp[tid];
        rv[tid] = sv[tid * TKn + pp];
        ri[tid] = si[tid * TKn + pp];
        rt[tid] = (short)tid;
        __syncthreads();
        for (int s = 128; s > 0; s >>= 1) {
            if (tid < s) {
                float v2 = rv[tid + s]; int i2 = ri[tid + s];
                if (v2 > rv[tid] || (v2 == rv[tid] && i2 < ri[tid])) {
                    rv[tid] = v2; ri[tid] = i2; rt[tid] = rt[tid + s];
                }
            }
            __syncthreads();
        }
        if (tid == 0) {
            tkv[row * TKn + sel] = rv[0];
            tki[row * TKn + sel] = ri[0];
            sp[rt[0]]++;
        }
        __syncthreads();
    }
}

// ---- per-row combine; warp-shuffle reductions; writes U,V bf16 splits -------
__global__ __launch_bounds__(256)
void combine_kernel(const float* __restrict__ EH, const float* __restrict__ ET,
                    const float* __restrict__ tkv, const int* __restrict__ tki,
                    bf16* __restrict__ Uh, bf16* __restrict__ Ul,
                    bf16* __restrict__ Vh, bf16* __restrict__ Vl)
{
    const int row = blockIdx.x;
    const int tid = threadIdx.x;
    const int wid = tid >> 5, lane = tid & 31;

    __shared__ float sh_eh[En];
    __shared__ float sh_nb[TKn][En];
    __shared__ float w[TKn]; __shared__ int idx[TKn];
    __shared__ float p[TKn]; __shared__ float q[TKn];
    __shared__ float wred[8][2 * TKn];

    if (tid < TKn) { w[tid] = tkv[row * TKn + tid]; idx[tid] = tki[row * TKn + tid]; }
    __syncthreads();

    for (int e = tid; e < En; e += 256) sh_eh[e] = EH[(size_t)row * En + e];
#pragma unroll
    for (int k = 0; k < TKn; k++) {
        const float* src = ET + (size_t)idx[k] * En;
        for (int e = tid; e < En; e += 256) sh_nb[k][e] = src[e];
    }
    if (tid == 0) {
        float mx = w[0];
        for (int k = 1; k < TKn; k++) mx = fmaxf(mx, w[k]);
        float s = 0.0f;
        for (int k = 0; k < TKn; k++) { p[k] = expf(w[k] - mx); s += p[k]; }
        float inv = 1.0f / s;
        for (int k = 0; k < TKn; k++) p[k] *= inv;
    }
    __syncthreads();

    float pn[TKn], pg[TKn];
#pragma unroll
    for (int k = 0; k < TKn; k++) { pn[k] = 0.0f; pg[k] = 0.0f; }
    for (int e = tid; e < En; e += 256) {
        const float eh = sh_eh[e];
#pragma unroll
        for (int k = 0; k < TKn; k++) {
            const float nb = sh_nb[k][e];
            pn[k] += nb;
            pg[k] += tanhf((2.0f - p[k]) * eh + p[k] * nb);
        }
    }
    // warp-level shuffle reduction, then one cross-warp stage
#pragma unroll
    for (int k = 0; k < TKn; k++) {
#pragma unroll
        for (int o = 16; o > 0; o >>= 1) {
            pn[k] += __shfl_xor_sync(0xffffffffu, pn[k], o);
            pg[k] += __shfl_xor_sync(0xffffffffu, pg[k], o);
        }
    }
    if (lane == 0) {
#pragma unroll
        for (int k = 0; k < TKn; k++) {
            wred[wid][k] = pn[k];
            wred[wid][TKn + k] = pg[k];
        }
    }
    __syncthreads();
    if (tid == 0) {
        float ka[TKn];
        float mx = -INFINITY;
#pragma unroll
        for (int k = 0; k < TKn; k++) {
            float sn = 0.0f, sg = 0.0f;
#pragma unroll
            for (int c = 0; c < 8; c++) { sn += wred[c][k]; sg += wred[c][TKn + k]; }
            ka[k] = sn * sg;
            mx = fmaxf(mx, ka[k]);
        }
        float s = 0.0f;
        for (int k = 0; k < TKn; k++) { q[k] = expf(ka[k] - mx); s += q[k]; }
        float inv = 1.0f / s;
        for (int k = 0; k < TKn; k++) q[k] *= inv;
    }
    __syncthreads();

    for (int e = tid; e < En; e += 256) {
        float en = 0.0f;
#pragma unroll
        for (int k = 0; k < TKn; k++) en = fmaf(q[k], sh_nb[k][e], en);
        const float eh = sh_eh[e];
        const size_t o = (size_t)row * En + e;
        const float u = eh + en, v = eh * en;
        const bf16 uh = __float2bfloat16(u);
        const bf16 vh = __float2bfloat16(v);
        Uh[o] = uh; Ul[o] = __float2bfloat16(u - __bfloat162float(uh));
        Vh[o] = vh; Vl[o] = __float2bfloat16(v - __bfloat162float(vh));
    }
}

// ---- g = G1 @ a2_w^T + a2_b -------------------------------------------------
__global__ void matvec_kernel(const float* __restrict__ G1,
                              const float* __restrict__ a2w,
                              const float* __restrict__ a2b,
                              float* __restrict__ gv)
{
    const int warp = (blockIdx.x * blockDim.x + threadIdx.x) >> 5;
    const int lane = threadIdx.x & 31;
    if (warp >= Mn) return;
    const float* rowp = G1 + (size_t)warp * (En / 2);
    float s = 0.0f;
    for (int j = lane; j < En / 2; j += 32) s = fmaf(rowp[j], a2w[j], s);
#pragma unroll
    for (int o = 16; o > 0; o >>= 1) s += __shfl_xor_sync(0xffffffffu, s, o);
    if (lane == 0) gv[warp] = s + a2b[0];
}

__global__ void softmax_att_kernel(const float* __restrict__ gv, float* __restrict__ att)
{
    __shared__ float red[256];
    const int tid = threadIdx.x;
    float mx = -INFINITY;
    for (int i = tid; i < Mn; i += 256) mx = fmaxf(mx, gv[i]);
    red[tid] = mx; __syncthreads();
    for (int s = 128; s > 0; s >>= 1) { if (tid < s) red[tid] = fmaxf(red[tid], red[tid + s]); __syncthreads(); }
    mx = red[0]; __syncthreads();
    float se = 0.0f;
    for (int i = tid; i < Mn; i += 256) se += expf(gv[i] - mx);
    red[tid] = se; __syncthreads();
    for (int s = 128; s > 0; s >>= 1) { if (tid < s) red[tid] += red[tid + s]; __syncthreads(); }
    const float inv = 1.0f / red[0];
    for (int i = tid; i < Mn; i += 256) att[i] = expf(gv[i] - mx) * inv;
}

__global__ void pool_ln_kernel(const float* __restrict__ part,
                               const float* __restrict__ g,
                               const float* __restrict__ b,
                               float* __restrict__ out)
{
    __shared__ float red[En];
    const int e = threadIdx.x;
    float s = 0.0f;
    for (int c = 0; c < 256; c++) s += part[c * En + e];
    red[e] = s; __syncthreads();
    for (int st = 256; st > 0; st >>= 1) { if (e < st) red[e] += red[e + st]; __syncthreads(); }
    const float mu = red[0] * (1.0f / (float)En);
    __syncthreads();
    const float d = s - mu;
    red[e] = d * d; __syncthreads();
    for (int st = 256; st > 0; st >>= 1) { if (e < st) red[e] += red[e + st]; __syncthreads(); }
    const float var = red[0] * (1.0f / (float)En);
    out[e] = d * rsqrtf(var + 1e-5f) * g[e] + b[e];
}

// --------------------------------------------------------------------------
extern "C" void kernel_launch(void* const* d_in, const int* in_sizes, int n_in,
                              void* d_out, int out_size)
{
    (void)in_sizes; (void)n_in; (void)out_size;
    const float* x    = (const float*)d_in[0];
    const float* fc1w = (const float*)d_in[1];
    const float* fc1b = (const float*)d_in[2];
    const float* whw  = (const float*)d_in[3];
    const float* whb  = (const float*)d_in[4];
    const float* wtw  = (const float*)d_in[5];
    const float* wtb  = (const float*)d_in[6];
    const float* l1w  = (const float*)d_in[7];
    const float* l1b  = (const float*)d_in[8];
    const float* l2w  = (const float*)d_in[9];
    const float* l2b  = (const float*)d_in[10];
    const float* a1w  = (const float*)d_in[11];
    const float* a1b  = (const float*)d_in[12];
    const float* a2w  = (const float*)d_in[13];
    const float* a2b  = (const float*)d_in[14];
    const float* lng  = (const float*)d_in[15];
    const float* lnb  = (const float*)d_in[16];
    float* out = (float*)d_out;

    float *H, *EH, *ET, *S, *TKV, *EMB, *G1, *GV, *ATT, *PART, *CM;
    bf16 *AH, *AL, *BH, *BL, *XH, *XL, *HH, *HL, *UH, *UL, *VH, *VL, *MH, *ML, *WH, *WL;
    int *TKI;
    cudaGetSymbolAddress((void**)&H,   g_H);
    cudaGetSymbolAddress((void**)&EH,  g_EH);
    cudaGetSymbolAddress((void**)&ET,  g_ET);
    cudaGetSymbolAddress((void**)&S,   g_S);
    cudaGetSymbolAddress((void**)&AH,  g_AH);
    cudaGetSymbolAddress((void**)&AL,  g_AL);
    cudaGetSymbolAddress((void**)&BH,  g_BH);
    cudaGetSymbolAddress((void**)&BL,  g_BL);
    cudaGetSymbolAddress((void**)&XH,  g_XH);
    cudaGetSymbolAddress((void**)&XL,  g_XL);
    cudaGetSymbolAddress((void**)&HH,  g_HH);
    cudaGetSymbolAddress((void**)&HL,  g_HL);
    cudaGetSymbolAddress((void**)&UH,  g_UH);
    cudaGetSymbolAddress((void**)&UL,  g_UL);
    cudaGetSymbolAddress((void**)&VH,  g_VH);
    cudaGetSymbolAddress((void**)&VL,  g_VL);
    cudaGetSymbolAddress((void**)&MH,  g_MH);
    cudaGetSymbolAddress((void**)&ML,  g_ML);
    cudaGetSymbolAddress((void**)&WH,  g_WH);
    cudaGetSymbolAddress((void**)&WL,  g_WL);
    cudaGetSymbolAddress((void**)&TKV, g_TKV);
    cudaGetSymbolAddress((void**)&TKI, g_TKI);
    cudaGetSymbolAddress((void**)&EMB, g_EMB);
    cudaGetSymbolAddress((void**)&G1,  g_G1);
    cudaGetSymbolAddress((void**)&GV,  g_GV);
    cudaGetSymbolAddress((void**)&ATT, g_ATT);
    cudaGetSymbolAddress((void**)&PART,g_PART);
    cudaGetSymbolAddress((void**)&CM,  g_CM);

    const float scale = 1.0f / sqrtf((float)En);

    cudaFuncSetAttribute(hgemm_nt<1, false, false>, cudaFuncAttributeMaxDynamicSharedMemorySize, 2 * STG_BYTES);
    cudaFuncSetAttribute(hgemm_nt<0, false, true >, cudaFuncAttributeMaxDynamicSharedMemorySize, 2 * STG_BYTES);
    cudaFuncSetAttribute(hgemm_nt<1, true,  true >, cudaFuncAttributeMaxDynamicSharedMemorySize, 2 * STG_BYTES);
    cudaFuncSetAttribute(attn_hmma_kernel, cudaFuncAttributeMaxDynamicSharedMemorySize, 2 * STG_BYTES);

    // 1) h = lrelu(x @ fc1^T + b)
    split_kernel<<<(Mn * INn + 255) / 256, 256>>>(x, Mn * INn, XH, XL);
    split_kernel<<<(En * INn + 255) / 256, 256>>>(fc1w, En * INn, WH, WL);
    hgemm_nt<1, false, false><<<dim3(En / 128, Mn / 128), 256, 2 * STG_BYTES>>>(
        XH, XL, WH, WL, fc1b, H, nullptr, nullptr, 0.0f, En, INn);
    // 2) h = (h + colmean(h)) * 0.5  -> split
    colred_kernel<false><<<dim3(En / 128, 256), 128>>>(H, nullptr, PART, Mn, En);
    cmfin_kernel<<<1, En>>>(PART, CM);
    meanscale_split_kernel<<<(Mn * En) / 1024, 256>>>(H, CM, HH, HL);
    // 3) e_h (emits scaled split = attn A), e_t (emits split = attn B)
    split_kernel<<<(En * En + 255) / 256, 256>>>(whw, En * En, WH, WL);
    hgemm_nt<0, false, true><<<dim3(En / 128, Mn / 128), 256, 2 * STG_BYTES>>>(
        HH, HL, WH, WL, whb, EH, AH, AL, scale, En, En);
    split_kernel<<<(En * En + 255) / 256, 256>>>(wtw, En * En, WH, WL);
    hgemm_nt<0, false, true><<<dim3(En / 128, Mn / 128), 256, 2 * STG_BYTES>>>(
        HH, HL, WH, WL, wtb, ET, BH, BL, 1.0f, En, En);
    // 4) S = (e_h * scale) @ e_t^T
    attn_hmma_kernel<<<dim3(Mn / 128, Mn / 128), 256, 2 * STG_BYTES>>>(AH, AL, BH, BL, S);
    // 5) per-row top-6
    topk_kernel<<<Mn, 256>>>(S, TKV, TKI);
    // 6) combine -> U, V bf16 splits
    combine_kernel<<<Mn, 256>>>(EH, ET, TKV, TKI, UH, UL, VH, VL);
    // 7) emb = lrelu(U@l1^T+b) + lrelu(V@l2^T+b)
    split_kernel<<<(En * En + 255) / 256, 256>>>(l1w, En * En, WH, WL);
    hgemm_nt<1, false, false><<<dim3(En / 128, Mn / 128), 256, 2 * STG_BYTES>>>(
        UH, UL, WH, WL, l1b, EMB, nullptr, nullptr, 0.0f, En, En);
    split_kernel<<<(En * En + 255) / 256, 256>>>(l2w, En * En, WH, WL);
    hgemm_nt<1, true, true><<<dim3(En / 128, Mn / 128), 256, 2 * STG_BYTES>>>(
        VH, VL, WH, WL, l2b, EMB, MH, ML, 1.0f, En, En);
    // 8) readout gate
    split_kernel<<<((En / 2) * En + 255) / 256, 256>>>(a1w, (En / 2) * En, WH, WL);
    hgemm_nt<1, false, false><<<dim3((En / 2) / 128, Mn / 128), 256, 2 * STG_BYTES>>>(
        MH, ML, WH, WL, a1b, G1, nullptr, nullptr, 0.0f, En / 2, En);
    matvec_kernel<<<Mn / 8, 256>>>(G1, a2w, a2b, GV);
    // 9) softmax over nodes, weighted pool, layernorm
    softmax_att_kernel<<<1, 256>>>(GV, ATT);
    colred_kernel<true><<<dim3(En / 128, 256), 128>>>(EMB, ATT, PART, Mn, En);
    pool_ln_kernel<<<1, En>>>(PART, lng, lnb, out);
}

// round 7
// speedup vs baseline: 1.6181x; 1.1311x over previous
#include <cuda_runtime.h>
#include <cuda_bf16.h>
#include <math.h>
#include <stdint.h>

#define Mn  8192
#define En  512
#define INn 384
#define TKn 6
#define NTILE (Mn / 128)

typedef __nv_bfloat16 bf16;

// ------------------------- scratch (__device__ globals; no allocation) -----
__device__ float g_H  [Mn * En];
__device__ float g_EH [Mn * En];
__device__ float g_ET [Mn * En];
__device__ float g_S  [(size_t)Mn * Mn];
__device__ bf16  g_AH[Mn * En];
__device__ bf16  g_AL[Mn * En];
__device__ bf16  g_BH[Mn * En];
__device__ bf16  g_BL[Mn * En];
__device__ bf16  g_XH[Mn * INn];
__device__ bf16  g_XL[Mn * INn];
__device__ bf16  g_HH[Mn * En];
__device__ bf16  g_HL[Mn * En];
__device__ bf16  g_UH[Mn * En];
__device__ bf16  g_UL[Mn * En];
__device__ bf16  g_VH[Mn * En];
__device__ bf16  g_VL[Mn * En];
__device__ bf16  g_MH[Mn * En];
__device__ bf16  g_ML[Mn * En];
__device__ bf16  g_WH[En * En];
__device__ bf16  g_WL[En * En];
__device__ float g_PMV[Mn * NTILE];      // per-(row,tile) max value
__device__ int   g_PMI[Mn * NTILE];      // per-(row,tile) argmax (global col)
__device__ float g_TKV[Mn * TKn];
__device__ int   g_TKI[Mn * TKn];
__device__ float g_EMB[Mn * En];
__device__ float g_G1 [Mn * (En / 2)];
__device__ float g_GV [Mn];
__device__ float g_ATT[Mn];
__device__ float g_PART[256 * En];
__device__ float g_CM [En];

// ===================== helpers ==============================================
__device__ __forceinline__ uint32_t smem_u32(const void* p) {
    uint32_t a;
    asm("{ .reg .u64 t; cvta.to.shared.u64 t, %1; cvt.u32.u64 %0, t; }"
        : "=r"(a) : "l"(p));
    return a;
}
__device__ __forceinline__ void cp_async16(uint32_t dst, const void* src) {
    asm volatile("cp.async.cg.shared.global [%0], [%1], 16;"
                 :: "r"(dst), "l"(src) : "memory");
}
__device__ __forceinline__ void cp_commit() {
    asm volatile("cp.async.commit_group;" ::: "memory");
}
__device__ __forceinline__ void cp_wait1() {
    asm volatile("cp.async.wait_group 1;" ::: "memory");
}
__device__ __forceinline__ void cp_wait0() {
    asm volatile("cp.async.wait_group 0;" ::: "memory");
}
__device__ __forceinline__ void ldm_x4(uint32_t& r0, uint32_t& r1,
                                       uint32_t& r2, uint32_t& r3, uint32_t a) {
    asm volatile("ldmatrix.sync.aligned.m8n8.x4.shared.b16 {%0,%1,%2,%3}, [%4];"
                 : "=r"(r0), "=r"(r1), "=r"(r2), "=r"(r3) : "r"(a));
}
__device__ __forceinline__ void mma16816(float* d, const uint32_t* a, const uint32_t* b) {
    asm volatile(
        "mma.sync.aligned.m16n8k16.row.col.f32.bf16.bf16.f32 "
        "{%0,%1,%2,%3}, {%4,%5,%6,%7}, {%8,%9}, {%0,%1,%2,%3};"
        : "+f"(d[0]), "+f"(d[1]), "+f"(d[2]), "+f"(d[3])
        : "r"(a[0]), "r"(a[1]), "r"(a[2]), "r"(a[3]), "r"(b[0]), "r"(b[1]));
}
__device__ __forceinline__ uint32_t sw128(uint32_t o) { return o ^ ((o >> 3) & 0x70); }
__device__ __forceinline__ bool better(float v2, int i2, float v1, int i1) {
    return (v2 > v1) || (v2 == v1 && i2 < i1);
}

// ===================== split fp32 -> (bf16 hi, bf16 lo), float4 =============
__global__ void split_kernel(const float* __restrict__ X, int n4,
                             bf16* __restrict__ hi, bf16* __restrict__ lo)
{
    const int i = blockIdx.x * blockDim.x + threadIdx.x;
    if (i >= n4) return;
    const float4 a = *(const float4*)(X + i * 4);
    const float v[4] = { a.x, a.y, a.z, a.w };
    bf16 h[4], l[4];
#pragma unroll
    for (int k = 0; k < 4; k++) {
        h[k] = __float2bfloat16(v[k]);
        l[k] = __float2bfloat16(v[k] - __bfloat162float(h[k]));
    }
    *(__nv_bfloat162*)(hi + i * 4)     = __nv_bfloat162(h[0], h[1]);
    *(__nv_bfloat162*)(hi + i * 4 + 2) = __nv_bfloat162(h[2], h[3]);
    *(__nv_bfloat162*)(lo + i * 4)     = __nv_bfloat162(l[0], l[1]);
    *(__nv_bfloat162*)(lo + i * 4 + 2) = __nv_bfloat162(l[2], l[3]);
}

// ===================== generic HMMA split GEMM ==============================
#define STG_BYTES 65536
#define OFF_AH    0
#define OFF_AL    16384
#define OFF_BH    32768
#define OFF_BL    49152

template<int ACT, bool ADD_C, bool WSPLIT>
__global__ __launch_bounds__(256)
void hgemm_nt(const bf16* __restrict__ Ah, const bf16* __restrict__ Al,
              const bf16* __restrict__ Bh, const bf16* __restrict__ Bl,
              const float* __restrict__ bias, float* __restrict__ C,
              bf16* __restrict__ Sh, bf16* __restrict__ Sl,
              float salpha, int N, int K)
{
    extern __shared__ char smem[];
    const uint32_t sb = smem_u32(smem);
    const int tid = threadIdx.x;
    const int w = tid >> 5, l = tid & 31;
    const int m0 = (w & 1) * 64;
    const int n0 = (w >> 1) * 32;
    const int arow0 = blockIdx.y * 128;
    const int brow0 = blockIdx.x * 128;

    const int g  = l >> 3, lr = l & 7;
    const int ar  = (g & 1) * 8 + lr;
    const int acb = (g >> 1) * 16;
    const int br  = (g >> 1) * 8 + lr;
    const int bcb = (g & 1) * 16;

    float acc[4][4][4];
#pragma unroll
    for (int i = 0; i < 4; i++)
#pragma unroll
        for (int j = 0; j < 4; j++)
#pragma unroll
            for (int q = 0; q < 4; q++) acc[i][j][q] = 0.0f;

    auto load_stage = [&](int kc, int s) {
        const uint32_t base = sb + s * STG_BYTES;
        const int kof = kc * 64;
#pragma unroll
        for (int i = 0; i < 4; i++) {
            const int v = tid + i * 256;
            const int r = v >> 3;
            const int cb = (v & 7) * 16;
            const uint32_t sw = sw128((uint32_t)(r * 128 + cb));
            const size_t ga = (size_t)(arow0 + r) * K + kof + (v & 7) * 8;
            const size_t gb = (size_t)(brow0 + r) * K + kof + (v & 7) * 8;
            cp_async16(base + OFF_AH + sw, Ah + ga);
            cp_async16(base + OFF_AL + sw, Al + ga);
            cp_async16(base + OFF_BH + sw, Bh + gb);
            cp_async16(base + OFF_BL + sw, Bl + gb);
        }
        cp_commit();
    };

    const int NKC = K >> 6;
    load_stage(0, 0);

    for (int kc = 0; kc < NKC; kc++) {
        if (kc + 1 < NKC) { load_stage(kc + 1, (kc + 1) & 1); cp_wait1(); }
        else              { cp_wait0(); }
        __syncthreads();

        const uint32_t base = sb + (kc & 1) * STG_BYTES;
#pragma unroll
        for (int ks = 0; ks < 4; ks++) {
            const int kb = ks * 32;
            uint32_t fah[4][4], fal[4][4];
#pragma unroll
            for (int mf = 0; mf < 4; mf++) {
                const uint32_t ro = (uint32_t)((m0 + mf * 16 + ar) * 128 + kb + acb);
                ldm_x4(fah[mf][0], fah[mf][1], fah[mf][2], fah[mf][3],
                       base + OFF_AH + sw128(ro));
                ldm_x4(fal[mf][0], fal[mf][1], fal[mf][2], fal[mf][3],
                       base + OFF_AL + sw128(ro));
            }
            uint32_t fbh[4][2], fbl[4][2];
#pragma unroll
            for (int np = 0; np < 2; np++) {
                const uint32_t ro = (uint32_t)((n0 + np * 16 + br) * 128 + kb + bcb);
                uint32_t r0, r1, r2, r3;
                ldm_x4(r0, r1, r2, r3, base + OFF_BH + sw128(ro));
                fbh[np * 2 + 0][0] = r0; fbh[np * 2 + 0][1] = r1;
                fbh[np * 2 + 1][0] = r2; fbh[np * 2 + 1][1] = r3;
                ldm_x4(r0, r1, r2, r3, base + OFF_BL + sw128(ro));
                fbl[np * 2 + 0][0] = r0; fbl[np * 2 + 0][1] = r1;
                fbl[np * 2 + 1][0] = r2; fbl[np * 2 + 1][1] = r3;
            }
#pragma unroll
            for (int mf = 0; mf < 4; mf++)
#pragma unroll
                for (int nf = 0; nf < 4; nf++) {
                    mma16816(acc[mf][nf], fah[mf], fbh[nf]);
                    mma16816(acc[mf][nf], fah[mf], fbl[nf]);
                    mma16816(acc[mf][nf], fal[mf], fbh[nf]);
                }
        }
        __syncthreads();
    }

    const int qr = l >> 2, qc = (l & 3) * 2;
#pragma unroll
    for (int mf = 0; mf < 4; mf++) {
#pragma unroll
        for (int nf = 0; nf < 4; nf++) {
            const int col = brow0 + n0 + nf * 8 + qc;
            const float b0 = bias ? bias[col] : 0.0f;
            const float b1 = bias ? bias[col + 1] : 0.0f;
#pragma unroll
            for (int half = 0; half < 2; half++) {
                const int row = arow0 + m0 + mf * 16 + qr + half * 8;
                float v0 = acc[mf][nf][half * 2 + 0] + b0;
                float v1 = acc[mf][nf][half * 2 + 1] + b1;
                if (ACT == 1) {
                    v0 = v0 > 0.0f ? v0 : 0.01f * v0;
                    v1 = v1 > 0.0f ? v1 : 0.01f * v1;
                }
                const size_t o = (size_t)row * N + col;
                if (ADD_C) {
                    float2 old = *(float2*)(C + o);
                    v0 += old.x; v1 += old.y;
                }
                *(float2*)(C + o) = make_float2(v0, v1);
                if (WSPLIT) {
                    const float s0 = v0 * salpha, s1 = v1 * salpha;
                    const bf16 h0 = __float2bfloat16(s0);
                    const bf16 h1 = __float2bfloat16(s1);
                    Sh[o]     = h0;
                    Sh[o + 1] = h1;
                    Sl[o]     = __float2bfloat16(s0 - __bfloat162float(h0));
                    Sl[o + 1] = __float2bfloat16(s1 - __bfloat162float(h1));
                }
            }
        }
    }
}

// ===================== HMMA attn GEMM: S = A@B^T + per-tile row max =========
__global__ __launch_bounds__(256)
void attn_hmma_kernel(const bf16* __restrict__ Ah, const bf16* __restrict__ Al,
                      const bf16* __restrict__ Bh, const bf16* __restrict__ Bl,
                      float* __restrict__ S,
                      float* __restrict__ PMV, int* __restrict__ PMI)
{
    extern __shared__ char smem[];
    const uint32_t sb = smem_u32(smem);
    const int tid = threadIdx.x;
    const int w = tid >> 5, l = tid & 31;
    const int m0 = (w & 1) * 64;
    const int n0 = (w >> 1) * 32;
    const int arow0 = blockIdx.y * 128;
    const int brow0 = blockIdx.x * 128;

    const int g  = l >> 3, lr = l & 7;
    const int ar  = (g & 1) * 8 + lr;
    const int acb = (g >> 1) * 16;
    const int br  = (g >> 1) * 8 + lr;
    const int bcb = (g & 1) * 16;

    float acc[4][4][4];
#pragma unroll
    for (int i = 0; i < 4; i++)
#pragma unroll
        for (int j = 0; j < 4; j++)
#pragma unroll
            for (int q = 0; q < 4; q++) acc[i][j][q] = 0.0f;

    auto load_stage = [&](int kc, int s) {
        const uint32_t base = sb + s * STG_BYTES;
        const int kof = kc * 64;
#pragma unroll
        for (int i = 0; i < 4; i++) {
            const int v = tid + i * 256;
            const int r = v >> 3;
            const int cb = (v & 7) * 16;
            const uint32_t sw = sw128((uint32_t)(r * 128 + cb));
            const size_t ga = (size_t)(arow0 + r) * En + kof + (v & 7) * 8;
            const size_t gb = (size_t)(brow0 + r) * En + kof + (v & 7) * 8;
            cp_async16(base + OFF_AH + sw, Ah + ga);
            cp_async16(base + OFF_AL + sw, Al + ga);
            cp_async16(base + OFF_BH + sw, Bh + gb);
            cp_async16(base + OFF_BL + sw, Bl + gb);
        }
        cp_commit();
    };

    load_stage(0, 0);
    const int NKC = En / 64;
    for (int kc = 0; kc < NKC; kc++) {
        if (kc + 1 < NKC) { load_stage(kc + 1, (kc + 1) & 1); cp_wait1(); }
        else              { cp_wait0(); }
        __syncthreads();

        const uint32_t base = sb + (kc & 1) * STG_BYTES;
#pragma unroll
        for (int ks = 0; ks < 4; ks++) {
            const int kb = ks * 32;
            uint32_t fah[4][4], fal[4][4];
#pragma unroll
            for (int mf = 0; mf < 4; mf++) {
                const uint32_t ro = (uint32_t)((m0 + mf * 16 + ar) * 128 + kb + acb);
                ldm_x4(fah[mf][0], fah[mf][1], fah[mf][2], fah[mf][3],
                       base + OFF_AH + sw128(ro));
                ldm_x4(fal[mf][0], fal[mf][1], fal[mf][2], fal[mf][3],
                       base + OFF_AL + sw128(ro));
            }
            uint32_t fbh[4][2], fbl[4][2];
#pragma unroll
            for (int np = 0; np < 2; np++) {
                const uint32_t ro = (uint32_t)((n0 + np * 16 + br) * 128 + kb + bcb);
                uint32_t r0, r1, r2, r3;
                ldm_x4(r0, r1, r2, r3, base + OFF_BH + sw128(ro));
                fbh[np * 2 + 0][0] = r0; fbh[np * 2 + 0][1] = r1;
                fbh[np * 2 + 1][0] = r2; fbh[np * 2 + 1][1] = r3;
                ldm_x4(r0, r1, r2, r3, base + OFF_BL + sw128(ro));
                fbl[np * 2 + 0][0] = r0; fbl[np * 2 + 0][1] = r1;
                fbl[np * 2 + 1][0] = r2; fbl[np * 2 + 1][1] = r3;
            }
#pragma unroll
            for (int mf = 0; mf < 4; mf++)
#pragma unroll
                for (int nf = 0; nf < 4; nf++) {
                    mma16816(acc[mf][nf], fah[mf], fbh[nf]);
                    mma16816(acc[mf][nf], fah[mf], fbl[nf]);
                    mma16816(acc[mf][nf], fal[mf], fbh[nf]);
                }
        }
        __syncthreads();
    }

    // write S tile
    const int qr = l >> 2, qc = (l & 3) * 2;
#pragma unroll
    for (int mf = 0; mf < 4; mf++) {
        const int row = arow0 + m0 + mf * 16 + qr;
#pragma unroll
        for (int nf = 0; nf < 4; nf++) {
            const int col = brow0 + n0 + nf * 8 + qc;
            *(float2*)(S + (size_t)row * Mn + col) =
                make_float2(acc[mf][nf][0], acc[mf][nf][1]);
            *(float2*)(S + (size_t)(row + 8) * Mn + col) =
                make_float2(acc[mf][nf][2], acc[mf][nf][3]);
        }
    }

    // per-row (within CTA tile) max + argmax  (pipeline smem is dead; reuse)
    float* smx = (float*)smem;                 // [128][4]
    int*   smi = (int*)(smem + 2048);          // [128][4]
#pragma unroll
    for (int mf = 0; mf < 4; mf++) {
#pragma unroll
        for (int half = 0; half < 2; half++) {
            const int rowl = m0 + mf * 16 + qr + half * 8;
            float bmx = -INFINITY; int bmi = 0x7fffffff;
#pragma unroll
            for (int nf = 0; nf < 4; nf++) {
#pragma unroll
                for (int q = 0; q < 2; q++) {
                    const float vv = acc[mf][nf][half * 2 + q];
                    const int col = n0 + nf * 8 + qc + q;
                    if (better(vv, col, bmx, bmi)) { bmx = vv; bmi = col; }
                }
            }
#pragma unroll
            for (int o = 1; o <= 2; o <<= 1) {
                const float ov = __shfl_xor_sync(0xffffffffu, bmx, o);
                const int   oi = __shfl_xor_sync(0xffffffffu, bmi, o);
                if (better(ov, oi, bmx, bmi)) { bmx = ov; bmi = oi; }
            }
            if ((l & 3) == 0) { smx[rowl * 4 + (w >> 1)] = bmx; smi[rowl * 4 + (w >> 1)] = bmi; }
        }
    }
    __syncthreads();
    if (tid < 128) {
        float bmx = smx[tid * 4]; int bmi = smi[tid * 4];
#pragma unroll
        for (int c = 1; c < 4; c++) {
            const float ov = smx[tid * 4 + c]; const int oi = smi[tid * 4 + c];
            if (better(ov, oi, bmx, bmi)) { bmx = ov; bmi = oi; }
        }
        const size_t o = (size_t)(arow0 + tid) * NTILE + blockIdx.x;
        PMV[o] = bmx;
        PMI[o] = brow0 + bmi;
    }
}

// ===================== per-row top-6 via tile-max threshold + rescan =========
__global__ __launch_bounds__(64)
void topk_sel_kernel(const float* __restrict__ S,
                     const float* __restrict__ PMV, const int* __restrict__ PMI,
                     float* __restrict__ tkv, int* __restrict__ tki)
{
    const int row = blockIdx.x;
    const int t = threadIdx.x;            // 0..63 (tile id)
    const int lane = t & 31, wp = t >> 5;

    const float mv = PMV[(size_t)row * NTILE + t];
    const int   mi = PMI[(size_t)row * NTILE + t];

    __shared__ float swv[2]; __shared__ int swi[2]; __shared__ int swt[2];
    __shared__ float sh_thr;
    __shared__ int   sh_win;
    __shared__ int   clist[NTILE];
    __shared__ int   sh_cn;
    __shared__ float sv[64 * TKn];
    __shared__ int   si[64 * TKn];
    __shared__ int   sp[64];

    // --- tournament #1: find 6th-largest tile max (threshold) ---
    bool alive = true;
    for (int sel = 0; sel < TKn; sel++) {
        float cv = alive ? mv : -INFINITY;
        int   ci = alive ? mi : 0x7fffffff;
        int   tt = t;
#pragma unroll
        for (int o = 16; o > 0; o >>= 1) {
            const float ov = __shfl_xor_sync(0xffffffffu, cv, o);
            const int   oi = __shfl_xor_sync(0xffffffffu, ci, o);
            const int   ot = __shfl_xor_sync(0xffffffffu, tt, o);
            if (better(ov, oi, cv, ci)) { cv = ov; ci = oi; tt = ot; }
        }
        if (lane == 0) { swv[wp] = cv; swi[wp] = ci; swt[wp] = tt; }
        __syncthreads();
        if (t == 0) {
            int wi = better(swv[1], swi[1], swv[0], swi[0]) ? 1 : 0;
            sh_thr = swv[wi];
            sh_win = swt[wi];
        }
        __syncthreads();
        if (t == sh_win) alive = false;
    }
    const float thr = sh_thr;   // 6th-largest tile max

    // --- candidate tiles: max >= thr (value compare; superset incl. ties) ---
    if (t == 0) sh_cn = 0;
    __syncthreads();
    if (mv >= thr) { const int p = atomicAdd(&sh_cn, 1); clist[p] = t; }
    __syncthreads();
    const int cn = sh_cn;

    // --- rescan candidate tiles: each thread covers 2 cols per tile ---
    float lv[TKn]; int li[TKn];
#pragma unroll
    for (int k = 0; k < TKn; k++) { lv[k] = -INFINITY; li[k] = 0x7fffffff; }
    for (int c = 0; c < cn; c++) {
        const int tile = clist[c];
        const int col = tile * 128 + t * 2;
        const float2 vv = *(const float2*)(S + (size_t)row * Mn + col);
        const float vals[2] = { vv.x, vv.y };
#pragma unroll
        for (int q = 0; q < 2; q++) {
            const float v = vals[q];
            if (v > lv[TKn - 1] ||
                (v == lv[TKn - 1] && col + q < li[TKn - 1])) {
                lv[TKn - 1] = v; li[TKn - 1] = col + q;
#pragma unroll
                for (int k = TKn - 1; k > 0; k--) {
                    if (better(lv[k], li[k], lv[k - 1], li[k - 1])) {
                        float tv = lv[k]; lv[k] = lv[k - 1]; lv[k - 1] = tv;
                        int   ti = li[k]; li[k] = li[k - 1]; li[k - 1] = ti;
                    }
                }
            }
        }
    }

    // --- tournament #2: exact top-6 over per-thread lists ---
#pragma unroll
    for (int k = 0; k < TKn; k++) { sv[t * TKn + k] = lv[k]; si[t * TKn + k] = li[k]; }
    sp[t] = 0;
    __syncthreads();
    for (int sel = 0; sel < TKn; sel++) {
        const int pp = sp[t];
        float cv = sv[t * TKn + pp];
        int   ci = si[t * TKn + pp];
        int   tt = t;
#pragma unroll
        for (int o = 16; o > 0; o >>= 1) {
            const float ov = __shfl_xor_sync(0xffffffffu, cv, o);
            const int   oi = __shfl_xor_sync(0xffffffffu, ci, o);
            const int   ot = __shfl_xor_sync(0xffffffffu, tt, o);
            if (better(ov, oi, cv, ci)) { cv = ov; ci = oi; tt = ot; }
        }
        if (lane == 0) { swv[wp] = cv; swi[wp] = ci; swt[wp] = tt; }
        __syncthreads();
        if (t == 0) {
            int wi = better(swv[1], swi[1], swv[0], swi[0]) ? 1 : 0;
            tkv[row * TKn + sel] = swv[wi];
            tki[row * TKn + sel] = swi[wi];
            sh_win = swt[wi];
        }
        __syncthreads();
        if (t == sh_win && sp[t] < TKn - 1) sp[t]++;
        __syncthreads();
    }
}

// ---- column partial reduce (optionally row-weighted) -----------------------
template<bool W>
__global__ void colred_kernel(const float* __restrict__ X,
                              const float* __restrict__ wgt,
                              float* __restrict__ part, int rows, int cols)
{
    const int col   = blockIdx.x * blockDim.x + threadIdx.x;
    const int chunk = blockIdx.y;
    const int rpc   = rows / gridDim.y;
    const int r0    = chunk * rpc;
    float s = 0.0f;
    for (int r = r0; r < r0 + rpc; r++) {
        float v = X[(size_t)r * cols + col];
        if (W) v *= wgt[r];
        s += v;
    }
    part[chunk * cols + col] = s;
}

__global__ void cmfin_kernel(const float* __restrict__ part, float* __restrict__ cm)
{
    const int e = threadIdx.x;
    float s = 0.0f;
    for (int c = 0; c < 256; c++) s += part[c * En + e];
    cm[e] = s * (1.0f / (float)Mn);
}

// ---- h = (h + colmean)*0.5, write bf16 split (vectorized) -------------------
__global__ void meanscale_split_kernel(const float* __restrict__ H,
                                       const float* __restrict__ cm,
                                       bf16* __restrict__ hh, bf16* __restrict__ hl)
{
    const int i4 = (blockIdx.x * blockDim.x + threadIdx.x) * 4;
    const int e = i4 & (En - 1);
    const float4 hv = *(const float4*)(H + i4);
    const float4 cv = *(const float4*)(cm + e);
    float v[4] = { (hv.x + cv.x) * 0.5f, (hv.y + cv.y) * 0.5f,
                   (hv.z + cv.z) * 0.5f, (hv.w + cv.w) * 0.5f };
    bf16 hi[4], lo[4];
#pragma unroll
    for (int k = 0; k < 4; k++) {
        hi[k] = __float2bfloat16(v[k]);
        lo[k] = __float2bfloat16(v[k] - __bfloat162float(hi[k]));
    }
    *(__nv_bfloat162*)(hh + i4)     = __nv_bfloat162(hi[0], hi[1]);
    *(__nv_bfloat162*)(hh + i4 + 2) = __nv_bfloat162(hi[2], hi[3]);
    *(__nv_bfloat162*)(hl + i4)     = __nv_bfloat162(lo[0], lo[1]);
    *(__nv_bfloat162*)(hl + i4 + 2) = __nv_bfloat162(lo[2], lo[3]);
}

// ---- per-row combine; warp-shuffle reductions; writes U,V bf16 splits -------
__global__ __launch_bounds__(256)
void combine_kernel(const float* __restrict__ EH, const float* __restrict__ ET,
                    const float* __restrict__ tkv, const int* __restrict__ tki,
                    bf16* __restrict__ Uh, bf16* __restrict__ Ul,
                    bf16* __restrict__ Vh, bf16* __restrict__ Vl)
{
    const int row = blockIdx.x;
    const int tid = threadIdx.x;
    const int wid = tid >> 5, lane = tid & 31;

    __shared__ float sh_eh[En];
    __shared__ float sh_nb[TKn][En];
    __shared__ float w[TKn]; __shared__ int idx[TKn];
    __shared__ float p[TKn]; __shared__ float q[TKn];
    __shared__ float wred[8][2 * TKn];

    if (tid < TKn) { w[tid] = tkv[row * TKn + tid]; idx[tid] = tki[row * TKn + tid]; }
    __syncthreads();

    for (int e = tid; e < En; e += 256) sh_eh[e] = EH[(size_t)row * En + e];
#pragma unroll
    for (int k = 0; k < TKn; k++) {
        const float* src = ET + (size_t)idx[k] * En;
        for (int e = tid; e < En; e += 256) sh_nb[k][e] = src[e];
    }
    if (tid == 0) {
        float mx = w[0];
        for (int k = 1; k < TKn; k++) mx = fmaxf(mx, w[k]);
        float s = 0.0f;
        for (int k = 0; k < TKn; k++) { p[k] = expf(w[k] - mx); s += p[k]; }
        float inv = 1.0f / s;
        for (int k = 0; k < TKn; k++) p[k] *= inv;
    }
    __syncthreads();

    float pn[TKn], pg[TKn];
#pragma unroll
    for (int k = 0; k < TKn; k++) { pn[k] = 0.0f; pg[k] = 0.0f; }
    for (int e = tid; e < En; e += 256) {
        const float eh = sh_eh[e];
#pragma unroll
        for (int k = 0; k < TKn; k++) {
            const float nb = sh_nb[k][e];
            pn[k] += nb;
            pg[k] += tanhf((2.0f - p[k]) * eh + p[k] * nb);
        }
    }
#pragma unroll
    for (int k = 0; k < TKn; k++) {
#pragma unroll
        for (int o = 16; o > 0; o >>= 1) {
            pn[k] += __shfl_xor_sync(0xffffffffu, pn[k], o);
            pg[k] += __shfl_xor_sync(0xffffffffu, pg[k], o);
        }
    }
    if (lane == 0) {
#pragma unroll
        for (int k = 0; k < TKn; k++) {
            wred[wid][k] = pn[k];
            wred[wid][TKn + k] = pg[k];
        }
    }
    __syncthreads();
    if (tid == 0) {
        float ka[TKn];
        float mx = -INFINITY;
#pragma unroll
        for (int k = 0; k < TKn; k++) {
            float sn = 0.0f, sg = 0.0f;
#pragma unroll
            for (int c = 0; c < 8; c++) { sn += wred[c][k]; sg += wred[c][TKn + k]; }
            ka[k] = sn * sg;
            mx = fmaxf(mx, ka[k]);
        }
        float s = 0.0f;
        for (int k = 0; k < TKn; k++) { q[k] = expf(ka[k] - mx); s += q[k]; }
        float inv = 1.0f / s;
        for (int k = 0; k < TKn; k++) q[k] *= inv;
    }
    __syncthreads();

    for (int e = tid; e < En; e += 256) {
        float en = 0.0f;
#pragma unroll
        for (int k = 0; k < TKn; k++) en = fmaf(q[k], sh_nb[k][e], en);
        const float eh = sh_eh[e];
        const size_t o = (size_t)row * En + e;
        const float u = eh + en, v = eh * en;
        const bf16 uh = __float2bfloat16(u);
        const bf16 vh = __float2bfloat16(v);
        Uh[o] = uh; Ul[o] = __float2bfloat16(u - __bfloat162float(uh));
        Vh[o] = vh; Vl[o] = __float2bfloat16(v - __bfloat162float(vh));
    }
}

// ---- g = G1 @ a2_w^T + a2_b -------------------------------------------------
__global__ void matvec_kernel(const float* __restrict__ G1,
                              const float* __restrict__ a2w,
                              const float* __restrict__ a2b,
                              float* __restrict__ gv)
{
    const int warp = (blockIdx.x * blockDim.x + threadIdx.x) >> 5;
    const int lane = threadIdx.x & 31;
    if (warp >= Mn) return;
    const float* rowp = G1 + (size_t)warp * (En / 2);
    float s = 0.0f;
    for (int j = lane; j < En / 2; j += 32) s = fmaf(rowp[j], a2w[j], s);
#pragma unroll
    for (int o = 16; o > 0; o >>= 1) s += __shfl_xor_sync(0xffffffffu, s, o);
    if (lane == 0) gv[warp] = s + a2b[0];
}

__global__ void softmax_att_kernel(const float* __restrict__ gv, float* __restrict__ att)
{
    __shared__ float red[256];
    const int tid = threadIdx.x;
    float mx = -INFINITY;
    for (int i = tid; i < Mn; i += 256) mx = fmaxf(mx, gv[i]);
    red[tid] = mx; __syncthreads();
    for (int s = 128; s > 0; s >>= 1) { if (tid < s) red[tid] = fmaxf(red[tid], red[tid + s]); __syncthreads(); }
    mx = red[0]; __syncthreads();
    float se = 0.0f;
    for (int i = tid; i < Mn; i += 256) se += expf(gv[i] - mx);
    red[tid] = se; __syncthreads();
    for (int s = 128; s > 0; s >>= 1) { if (tid < s) red[tid] += red[tid + s]; __syncthreads(); }
    const float inv = 1.0f / red[0];
    for (int i = tid; i < Mn; i += 256) att[i] = expf(gv[i] - mx) * inv;
}

__global__ void pool_ln_kernel(const float* __restrict__ part,
                               const float* __restrict__ g,
                               const float* __restrict__ b,
                               float* __restrict__ out)
{
    __shared__ float red[En];
    const int e = threadIdx.x;
    float s = 0.0f;
    for (int c = 0; c < 256; c++) s += part[c * En + e];
    red[e] = s; __syncthreads();
    for (int st = 256; st > 0; st >>= 1) { if (e < st) red[e] += red[e + st]; __syncthreads(); }
    const float mu = red[0] * (1.0f / (float)En);
    __syncthreads();
    const float d = s - mu;
    red[e] = d * d; __syncthreads();
    for (int st = 256; st > 0; st >>= 1) { if (e < st) red[e] += red[e + st]; __syncthreads(); }
    const float var = red[0] * (1.0f / (float)En);
    out[e] = d * rsqrtf(var + 1e-5f) * g[e] + b[e];
}

// --------------------------------------------------------------------------
extern "C" void kernel_launch(void* const* d_in, const int* in_sizes, int n_in,
                              void* d_out, int out_size)
{
    (void)in_sizes; (void)n_in; (void)out_size;
    const float* x    = (const float*)d_in[0];
    const float* fc1w = (const float*)d_in[1];
    const float* fc1b = (const float*)d_in[2];
    const float* whw  = (const float*)d_in[3];
    const float* whb  = (const float*)d_in[4];
    const float* wtw  = (const float*)d_in[5];
    const float* wtb  = (const float*)d_in[6];
    const float* l1w  = (const float*)d_in[7];
    const float* l1b  = (const float*)d_in[8];
    const float* l2w  = (const float*)d_in[9];
    const float* l2b  = (const float*)d_in[10];
    const float* a1w  = (const float*)d_in[11];
    const float* a1b  = (const float*)d_in[12];
    const float* a2w  = (const float*)d_in[13];
    const float* a2b  = (const float*)d_in[14];
    const float* lng  = (const float*)d_in[15];
    const float* lnb  = (const float*)d_in[16];
    float* out = (float*)d_out;

    float *H, *EH, *ET, *S, *PMV, *TKV, *EMB, *G1, *GV, *ATT, *PART, *CM;
    bf16 *AH, *AL, *BH, *BL, *XH, *XL, *HH, *HL, *UH, *UL, *VH, *VL, *MH, *ML, *WH, *WL;
    int *TKI, *PMI;
    cudaGetSymbolAddress((void**)&H,   g_H);
    cudaGetSymbolAddress((void**)&EH,  g_EH);
    cudaGetSymbolAddress((void**)&ET,  g_ET);
    cudaGetSymbolAddress((void**)&S,   g_S);
    cudaGetSymbolAddress((void**)&PMV, g_PMV);
    cudaGetSymbolAddress((void**)&PMI, g_PMI);
    cudaGetSymbolAddress((void**)&AH,  g_AH);
    cudaGetSymbolAddress((void**)&AL,  g_AL);
    cudaGetSymbolAddress((void**)&BH,  g_BH);
    cudaGetSymbolAddress((void**)&BL,  g_BL);
    cudaGetSymbolAddress((void**)&XH,  g_XH);
    cudaGetSymbolAddress((void**)&XL,  g_XL);
    cudaGetSymbolAddress((void**)&HH,  g_HH);
    cudaGetSymbolAddress((void**)&HL,  g_HL);
    cudaGetSymbolAddress((void**)&UH,  g_UH);
    cudaGetSymbolAddress((void**)&UL,  g_UL);
    cudaGetSymbolAddress((void**)&VH,  g_VH);
    cudaGetSymbolAddress((void**)&VL,  g_VL);
    cudaGetSymbolAddress((void**)&MH,  g_MH);
    cudaGetSymbolAddress((void**)&ML,  g_ML);
    cudaGetSymbolAddress((void**)&WH,  g_WH);
    cudaGetSymbolAddress((void**)&WL,  g_WL);
    cudaGetSymbolAddress((void**)&TKV, g_TKV);
    cudaGetSymbolAddress((void**)&TKI, g_TKI);
    cudaGetSymbolAddress((void**)&EMB, g_EMB);
    cudaGetSymbolAddress((void**)&G1,  g_G1);
    cudaGetSymbolAddress((void**)&GV,  g_GV);
    cudaGetSymbolAddress((void**)&ATT, g_ATT);
    cudaGetSymbolAddress((void**)&PART,g_PART);
    cudaGetSymbolAddress((void**)&CM,  g_CM);

    const float scale = 1.0f / sqrtf((float)En);

    cudaFuncSetAttribute(hgemm_nt<1, false, false>, cudaFuncAttributeMaxDynamicSharedMemorySize, 2 * STG_BYTES);
    cudaFuncSetAttribute(hgemm_nt<0, false, true >, cudaFuncAttributeMaxDynamicSharedMemorySize, 2 * STG_BYTES);
    cudaFuncSetAttribute(hgemm_nt<1, true,  true >, cudaFuncAttributeMaxDynamicSharedMemorySize, 2 * STG_BYTES);
    cudaFuncSetAttribute(attn_hmma_kernel, cudaFuncAttributeMaxDynamicSharedMemorySize, 2 * STG_BYTES);

    // 1) h = lrelu(x @ fc1^T + b)
    split_kernel<<<(Mn * INn / 4 + 255) / 256, 256>>>(x, Mn * INn / 4, XH, XL);
    split_kernel<<<(En * INn / 4 + 255) / 256, 256>>>(fc1w, En * INn / 4, WH, WL);
    hgemm_nt<1, false, false><<<dim3(En / 128, Mn / 128), 256, 2 * STG_BYTES>>>(
        XH, XL, WH, WL, fc1b, H, nullptr, nullptr, 0.0f, En, INn);
    // 2) h = (h + colmean(h)) * 0.5  -> split
    colred_kernel<false><<<dim3(En / 128, 256), 128>>>(H, nullptr, PART, Mn, En);
    cmfin_kernel<<<1, En>>>(PART, CM);
    meanscale_split_kernel<<<(Mn * En) / 1024, 256>>>(H, CM, HH, HL);
    // 3) e_h (emits scaled split = attn A), e_t (emits split = attn B)
    split_kernel<<<(En * En / 4 + 255) / 256, 256>>>(whw, En * En / 4, WH, WL);
    hgemm_nt<0, false, true><<<dim3(En / 128, Mn / 128), 256, 2 * STG_BYTES>>>(
        HH, HL, WH, WL, whb, EH, AH, AL, scale, En, En);
    split_kernel<<<(En * En / 4 + 255) / 256, 256>>>(wtw, En * En / 4, WH, WL);
    hgemm_nt<0, false, true><<<dim3(En / 128, Mn / 128), 256, 2 * STG_BYTES>>>(
        HH, HL, WH, WL, wtb, ET, BH, BL, 1.0f, En, En);
    // 4) S = (e_h*scale) @ e_t^T + per-tile row maxima
    attn_hmma_kernel<<<dim3(NTILE, NTILE), 256, 2 * STG_BYTES>>>(AH, AL, BH, BL, S, PMV, PMI);
    // 5) top-6 via threshold + candidate-tile rescan
    topk_sel_kernel<<<Mn, 64>>>(S, PMV, PMI, TKV, TKI);
    // 6) combine -> U, V bf16 splits
    combine_kernel<<<Mn, 256>>>(EH, ET, TKV, TKI, UH, UL, VH, VL);
    // 7) emb = lrelu(U@l1^T+b) + lrelu(V@l2^T+b)
    split_kernel<<<(En * En / 4 + 255) / 256, 256>>>(l1w, En * En / 4, WH, WL);
    hgemm_nt<1, false, false><<<dim3(En / 128, Mn / 128), 256, 2 * STG_BYTES>>>(
        UH, UL, WH, WL, l1b, EMB, nullptr, nullptr, 0.0f, En, En);
    split_kernel<<<(En * En / 4 + 255) / 256, 256>>>(l2w, En * En / 4, WH, WL);
    hgemm_nt<1, true, true><<<dim3(En / 128, Mn / 128), 256, 2 * STG_BYTES>>>(
        VH, VL, WH, WL, l2b, EMB, MH, ML, 1.0f, En, En);
    // 8) readout gate
    split_kernel<<<((En / 2) * En / 4 + 255) / 256, 256>>>(a1w, (En / 2) * En / 4, WH, WL);
    hgemm_nt<1, false, false><<<dim3((En / 2) / 128, Mn / 128), 256, 2 * STG_BYTES>>>(
        MH, ML, WH, WL, a1b, G1, nullptr, nullptr, 0.0f, En / 2, En);
    matvec_kernel<<<Mn / 8, 256>>>(G1, a2w, a2b, GV);
    // 9) softmax over nodes, weighted pool, layernorm
    softmax_att_kernel<<<1, 256>>>(GV, ATT);
    colred_kernel<true><<<dim3(En / 128, 256), 128>>>(EMB, ATT, PART, Mn, En);
    pool_ln_kernel<<<1, En>>>(PART, lng, lnb, out);
}